// round 15
// baseline (speedup 1.0000x reference)
#include <cuda_runtime.h>
#include <cuda_bf16.h>
#include <math.h>

#define H      1024
#define H4     256          // H/4
#define VOUT   32000
#define ML     128
#define ATT    129          // ML + 1
#define ATTP   160          // padded attention length (multiple of 32)
#define GRID   148
#define BLOCK  512
#define WPB    (BLOCK/32)   // 16 warps per block
#define NWARPS (GRID*WPB)   // 2368
#define MAXSLOT 14          // max rows per warp

// ---------------- device scratch (static, no allocation) ----------------
__device__ float g_h[2][H];
__device__ float g_enc_T[(size_t)H * ATTP];    // transposed encoder outputs [j][t]
__device__ float g_M[(size_t)H * ATTP];        // M[i][t] = dot(W2[i], enc_out[t])
__device__ float g_gix[(size_t)ML * 3 * H];    // gix[t][r] = enc_Wih[r] @ emb[tok_t]
__device__ float g_attn[ATT];
__device__ float g_comb[H];
__device__ float g_logits[VOUT];
__device__ unsigned long long g_ptop[GRID][4]; // per-CTA top-4 packed
__device__ float g_psum[GRID];                 // per-CTA sumexp wrt its own max
__device__ unsigned g_wq[(size_t)VOUT * 256];  // 32MB int8 out_W (4 int8 / uint)
__device__ float g_wscale[VOUT];               // per-row dequant scale (maxabs/127)

__device__ unsigned g_bar_count = 0;
__device__ unsigned g_bar_gen   = 0;

// ---------------- helpers ----------------
__device__ __forceinline__ float wredsum(float v) {
#pragma unroll
    for (int o = 16; o > 0; o >>= 1) v += __shfl_xor_sync(0xffffffffu, v, o);
    return v;
}
__device__ __forceinline__ int wredsumi(int v) {
#pragma unroll
    for (int o = 16; o > 0; o >>= 1) v += __shfl_xor_sync(0xffffffffu, v, o);
    return v;
}
__device__ __forceinline__ float wredmax(float v) {
#pragma unroll
    for (int o = 16; o > 0; o >>= 1) v = fmaxf(v, __shfl_xor_sync(0xffffffffu, v, o));
    return v;
}
__device__ __forceinline__ unsigned long long wredmaxu64(unsigned long long v) {
#pragma unroll
    for (int o = 16; o > 0; o >>= 1) {
        unsigned long long q = __shfl_xor_sync(0xffffffffu, v, o);
        if (q > v) v = q;
    }
    return v;
}

__device__ __forceinline__ unsigned long long packf(float v, int idx) {
    unsigned u = __float_as_uint(v);
    u = (u & 0x80000000u) ? ~u : (u | 0x80000000u);   // totally ordered float bits
    return ((unsigned long long)u << 32) | (unsigned)(~(unsigned)idx); // tie -> lowest idx
}
__device__ __forceinline__ float unpack_max(unsigned long long p) {
    unsigned u = (unsigned)(p >> 32);
    unsigned b = (u & 0x80000000u) ? (u & 0x7fffffffu) : ~u;
    return __uint_as_float(b);
}
__device__ __forceinline__ int unpack_idx(unsigned long long p) {
    return (int)(~(unsigned)(p & 0xffffffffu));
}

__device__ __forceinline__ float dot4(float4 a, float4 b) {
    return a.x * b.x + a.y * b.y + a.z * b.z + a.w * b.w;
}

__device__ __forceinline__ unsigned q4(float4 v, float inv) {
    int a = __float2int_rn(v.x * inv);
    int b = __float2int_rn(v.y * inv);
    int c = __float2int_rn(v.z * inv);
    int d = __float2int_rn(v.w * inv);
    return (unsigned)(a & 0xFF) | ((unsigned)(b & 0xFF) << 8) |
           ((unsigned)(c & 0xFF) << 16) | ((unsigned)(d & 0xFF) << 24);
}

// insert p into descending top-4
__device__ __forceinline__ void top4_ins(unsigned long long& c0, unsigned long long& c1,
                                         unsigned long long& c2, unsigned long long& c3,
                                         unsigned long long p) {
    if (p > c0)      { c3 = c2; c2 = c1; c1 = c0; c0 = p; }
    else if (p > c1) { c3 = c2; c2 = c1; c1 = p; }
    else if (p > c2) { c3 = c2; c2 = p; }
    else if (p > c3) { c3 = p; }
}

// ---------------- grid-wide barrier ----------------
__device__ __forceinline__ unsigned ld_acq(unsigned* p) {
    unsigned v;
    asm volatile("ld.acquire.gpu.u32 %0, [%1];" : "=r"(v) : "l"(p) : "memory");
    return v;
}
__device__ __forceinline__ void st_rel(unsigned* p, unsigned v) {
    asm volatile("st.release.gpu.u32 [%0], %1;" :: "l"(p), "r"(v) : "memory");
}

__device__ __forceinline__ void gsync() {
    __syncthreads();
    if (threadIdx.x == 0) {
        unsigned gen = ld_acq(&g_bar_gen);
        __threadfence();
        if (atomicAdd(&g_bar_count, 1) == GRID - 1) {
            g_bar_count = 0;
            st_rel(&g_bar_gen, gen + 1);
        } else {
            while (ld_acq(&g_bar_gen) == gen) { }
        }
    }
    __syncthreads();
}

#define BAR6() asm volatile("bar.sync 1, 192;" ::: "memory")

// ---------------- shared-memory layout ----------------
struct Smem {
    float e[ATTP];                // attention softmax weights (zero-padded)
    float slot[WPB * MAXSLOT];    // raw logits per warp slot
    float red[WPB];               // warp-level reduction scratch
    float gh[8][4];               // Whh@h gate sums (+bhh), from prev D / prep
    float gi[8][4];               // hi-half partials exchange (B phase / encoder)
    float ca[8];                  // comb high-half partials (A exchange)
    unsigned hq[256];             // quantized h (4 int8 per uint)
    unsigned long long wtop[WPB][4];
    unsigned long long top4[4];
    unsigned long long cand[4];
    float bf[4];                  // scalar broadcasts (bf[3] = lse for delayed write)
    unsigned long long bu;
    int tk;                       // CTA-local current token
};

// ---------------- phases ----------------

// one-time: gix[t][r] = dot(enc_Wih[r], enc_emb[tokens[t]]) for all t, r.
// 8 token groups x 18 CTAs; warp = one token (emb cached in regs), rows
// strided by 18 with 4-row ILP. Accumulation order matches the old x-side
// dot (serial over 8 float4 chunks, then wredsum) -> bit-identical sums.
__device__ __forceinline__ void build_gix(
    const float* __restrict__ enc_Wih, const float* __restrict__ enc_emb,
    const int* __restrict__ tokens)
{
    int cta = (int)blockIdx.x;
    if (cta >= 144) return;
    int gtg = cta & 7;            // token group
    int j   = cta >> 3;           // 0..17: row residue
    int wib = threadIdx.x >> 5;
    int lane = threadIdx.x & 31;
    int t = gtg * 16 + wib;       // token 0..127

    const float4* e4 = (const float4*)(enc_emb + (size_t)tokens[t] * H);
    float4 ev[8];
#pragma unroll
    for (int i = 0; i < 8; i++) ev[i] = e4[lane + 32 * i];

    float* gx = g_gix + (size_t)t * (3 * H);

#pragma unroll 1
    for (int r0 = j; r0 < 3 * H; r0 += 72) {
        int r1 = r0 + 18, r2 = r0 + 36, r3 = r0 + 54;
        bool b1 = r1 < 3 * H, b2 = r2 < 3 * H, b3 = r3 < 3 * H;
        const float4* W0 = (const float4*)(enc_Wih + (size_t)r0 * H);
        const float4* W1 = (const float4*)(enc_Wih + (size_t)(b1 ? r1 : r0) * H);
        const float4* W2 = (const float4*)(enc_Wih + (size_t)(b2 ? r2 : r0) * H);
        const float4* W3 = (const float4*)(enc_Wih + (size_t)(b3 ? r3 : r0) * H);
        float a0 = 0.f, a1 = 0.f, a2 = 0.f, a3 = 0.f;
#pragma unroll
        for (int i = 0; i < 8; i++) {
            float4 w0 = W0[lane + 32 * i];
            float4 w1 = W1[lane + 32 * i];
            float4 w2 = W2[lane + 32 * i];
            float4 w3 = W3[lane + 32 * i];
            a0 += dot4(w0, ev[i]);
            a1 += dot4(w1, ev[i]);
            a2 += dot4(w2, ev[i]);
            a3 += dot4(w3, ev[i]);
        }
        a0 = wredsum(a0);
        a1 = wredsum(a1);
        a2 = wredsum(a2);
        a3 = wredsum(a3);
        if (lane == 0) {
            gx[r0] = a0;
            if (b1) gx[r1] = a1;
            if (b2) gx[r2] = a2;
            if (b3) gx[r3] = a3;
        }
    }
}

// Encoder GRU step using precomputed gix: only Whh@h remains, k-split across
// warp pairs (w0-6 low half / w8-14 high half), exchange via smem.
__device__ __forceinline__ void gru_phase_enc(
    const float* __restrict__ Whh,
    const float* __restrict__ bih, const float* __restrict__ bhh,
    const float* __restrict__ h, float* __restrict__ ho, int t, Smem* sm)
{
    int wib = threadIdx.x >> 5;
    int lane = threadIdx.x & 31;
    int wp = wib & 7;
    bool lo = (wib < 7);
    bool hi = (wib >= 8 && wib < 15);
    int row = wp * GRID + (int)blockIdx.x;
    bool act = (lo || hi) && row < H;

    float hr = 0.f, hz = 0.f, hn = 0.f;
    if (act) {
        const float4* h4 = (const float4*)h;
        const float4* W0 = (const float4*)(Whh + (size_t)row * H);
        const float4* W1 = (const float4*)(Whh + (size_t)(row + H) * H);
        const float4* W2 = (const float4*)(Whh + (size_t)(row + 2 * H) * H);
        int k0 = lo ? 0 : 128;
#pragma unroll 4
        for (int k = k0 + lane; k < k0 + 128; k += 32) {
            float4 hv = h4[k];
            hr += dot4(W0[k], hv);
            hz += dot4(W1[k], hv);
            hn += dot4(W2[k], hv);
        }
        hr = wredsum(hr); hz = wredsum(hz); hn = wredsum(hn);
        if (hi && lane == 0) {
            sm->gi[wp][0] = hr; sm->gi[wp][1] = hz; sm->gi[wp][2] = hn;
        }
    }
    __syncthreads();
    if (act && lo && lane == 0) {
        const float* gx = g_gix + (size_t)t * (3 * H);
        float ir  = gx[row]         + bih[row];
        float iz  = gx[row + H]     + bih[row + H];
        float inn = gx[row + 2 * H] + bih[row + 2 * H];
        float HR = hr + sm->gi[wp][0] + bhh[row];
        float HZ = hz + sm->gi[wp][1] + bhh[row + H];
        float HN = hn + sm->gi[wp][2] + bhh[row + 2 * H];
        float r = 1.f / (1.f + expf(-(ir + HR)));
        float z = 1.f / (1.f + expf(-(iz + HZ)));
        float n = tanhf(inn + r * HN);
        float hnew = (1.f - z) * n + z * h[row];
        ho[row] = hnew;
        g_enc_T[(size_t)row * ATTP + t] = hnew;
    }
}

// one-time after encoder: M[i][t] = dot(comb_W[i, H:2H], enc_out[t])
__device__ __forceinline__ void build_M(const float* __restrict__ comb_W)
{
    int wib = threadIdx.x >> 5;
    int lane = threadIdx.x & 31;
    if (wib >= 7) return;
    int row = wib * GRID + (int)blockIdx.x;
    if (row >= H) return;

    const float4* W2 = (const float4*)(comb_W + (size_t)row * 2 * H + H);
    float a0 = 0.f, a1 = 0.f, a2 = 0.f, a3 = 0.f, a4 = 0.f;
#pragma unroll 2
    for (int j4 = 0; j4 < H4; j4++) {
        float4 w = W2[j4];
        const float* E = g_enc_T + (size_t)(j4 * 4) * ATTP + lane;
#pragma unroll
        for (int c = 0; c < 4; c++) {
            float wc = (c == 0) ? w.x : (c == 1) ? w.y : (c == 2) ? w.z : w.w;
            const float* Ec = E + (size_t)c * ATTP;
            a0 += wc * Ec[0];
            a1 += wc * Ec[32];
            a2 += wc * Ec[64];
            a3 += wc * Ec[96];
            a4 += wc * Ec[128];
        }
    }
    float* Mr = g_M + (size_t)row * ATTP;
    Mr[lane]       = a0;
    Mr[lane + 32]  = a1;
    Mr[lane + 64]  = a2;
    Mr[lane + 96]  = a3;
    Mr[lane + 128] = a4;
}

// Whh@h gate sums for row wp (full k), writes sm->gh[wp] (+bhh)
__device__ __forceinline__ void whh_dots(
    const float* __restrict__ Whh, const float* __restrict__ bhh,
    const float* __restrict__ h, int wp, int lane, Smem* sm)
{
    int row = wp * GRID + (int)blockIdx.x;
    if (row >= H) return;
    const float4* h4 = (const float4*)h;
    const float4* W0 = (const float4*)(Whh + (size_t)row * H);
    const float4* W1 = (const float4*)(Whh + (size_t)(row + H) * H);
    const float4* W2 = (const float4*)(Whh + (size_t)(row + 2 * H) * H);
    float hr = 0.f, hz = 0.f, hn = 0.f;
#pragma unroll 4
    for (int k = lane; k < H4; k += 32) {
        float4 hv = h4[k];
        hr += dot4(W0[k], hv);
        hz += dot4(W1[k], hv);
        hn += dot4(W2[k], hv);
    }
    hr = wredsum(hr); hz = wredsum(hz); hn = wredsum(hn);
    if (lane == 0) {
        sm->gh[wp][0] = hr + bhh[row];
        sm->gh[wp][1] = hz + bhh[row + H];
        sm->gh[wp][2] = hn + bhh[row + 2 * H];
    }
}

// Phase A: softmax (w15) + comb rows k-split across warp pairs (w0-6 / w8-14).
__device__ __forceinline__ void comb_phase(
    const float* __restrict__ comb_W, const float* __restrict__ comb_b,
    const float* __restrict__ dec_emb, Smem* sm)
{
    int wib = threadIdx.x >> 5;
    int lane = threadIdx.x & 31;
    int tok = sm->tk;

    if (wib == 15) {
        float v[5];
        float mx = -INFINITY;
#pragma unroll
        for (int k = 0; k < 5; k++) {
            int idx = lane + 32 * k;
            v[k] = (idx < ATT) ? g_attn[idx] : -INFINITY;
            mx = fmaxf(mx, v[k]);
        }
        mx = wredmax(mx);
        float s = 0.f;
#pragma unroll
        for (int k = 0; k < 5; k++) {
            int idx = lane + 32 * k;
            float e = (idx < ATT) ? expf(v[k] - mx) : 0.f;
            sm->e[idx] = e;
            s += e;
        }
        s = wredsum(s);
        if (lane == 0) sm->bf[0] = 1.f / s;
    }

    int wp = wib & 7;
    bool lo = (wib < 7);
    bool hi = (wib >= 8 && wib < 15);
    int row = wp * GRID + (int)blockIdx.x;
    bool act = (lo || hi) && row < H;

    float a = 0.f;
    if (act) {
        const float4* W  = (const float4*)(comb_W + (size_t)row * 2 * H);
        const float4* e4 = (const float4*)(dec_emb + (size_t)tok * H);
        int k0 = lo ? 0 : 128;
#pragma unroll 4
        for (int k = k0 + lane; k < k0 + 128; k += 32) a += dot4(W[k], e4[k]);
        if (hi) {
            a = wredsum(a);
            if (lane == 0) sm->ca[wp] = a;
        }
    }
    __syncthreads();
    if (act && lo) {
        const float* Mr = g_M + (size_t)row * ATTP;
        float b = 0.f;
#pragma unroll
        for (int k = 0; k < 5; k++) {
            int t = lane + 32 * k;
            b += sm->e[t] * Mr[t];
        }
        float tot = a + b * sm->bf[0];
        tot = wredsum(tot);
        if (lane == 0)
            g_comb[row] = fmaxf(tot + sm->ca[wp] + comb_b[row], 0.f);
    }
}

// Phase B: gru finish — Wih@comb k-split + gates; warps 7,15 write prev output.
__device__ __forceinline__ void gru_fin_phase(
    const float* __restrict__ dec_Wih, const float* __restrict__ dec_bih,
    const float* __restrict__ hc, float* __restrict__ hn_out,
    float* __restrict__ out, int step, Smem* sm)
{
    int wib = threadIdx.x >> 5;
    int lane = threadIdx.x & 31;
    int wp = wib & 7;
    bool lo = (wib < 7);
    bool hi = (wib >= 8 && wib < 15);
    int row = wp * GRID + (int)blockIdx.x;
    bool act = (lo || hi) && row < H;

    float ir = 0.f, iz = 0.f, inn = 0.f;
    if (act) {
        const float4* x4 = (const float4*)g_comb;
        const float4* W0 = (const float4*)(dec_Wih + (size_t)row * H);
        const float4* W1 = (const float4*)(dec_Wih + (size_t)(row + H) * H);
        const float4* W2 = (const float4*)(dec_Wih + (size_t)(row + 2 * H) * H);
        int k0 = lo ? 0 : 128;
#pragma unroll 4
        for (int k = k0 + lane; k < k0 + 128; k += 32) {
            float4 xv = x4[k];
            ir  += dot4(W0[k], xv);
            iz  += dot4(W1[k], xv);
            inn += dot4(W2[k], xv);
        }
        ir = wredsum(ir); iz = wredsum(iz); inn = wredsum(inn);
        if (hi && lane == 0) {
            sm->gi[wp][0] = ir; sm->gi[wp][1] = iz; sm->gi[wp][2] = inn;
        }
    } else if ((wib == 7 || wib == 15) && step > 0) {
        float lse = sm->bf[3];
        int wt = (wib == 7 ? lane : 32 + lane);
        for (int g = (int)blockIdx.x * 64 + wt; g < VOUT; g += GRID * 64)
            out[(size_t)(step - 1) * VOUT + g] = g_logits[g] - lse;
    }
    __syncthreads();
    if (act && lo && lane == 0) {
        float IR = ir + sm->gi[wp][0] + dec_bih[row];
        float IZ = iz + sm->gi[wp][1] + dec_bih[row + H];
        float IN = inn + sm->gi[wp][2] + dec_bih[row + 2 * H];
        float hr = sm->gh[wp][0];
        float hz = sm->gh[wp][1];
        float hn = sm->gh[wp][2];
        float r = 1.f / (1.f + expf(-(IR + hr)));
        float z = 1.f / (1.f + expf(-(IZ + hz)));
        float n = tanhf(IN + r * hn);
        hn_out[row] = (1.f - z) * n + z * hc[row];
    }
}

// Phase C: logits GEMV on int8 weights
__device__ __forceinline__ void logits_phase(
    const float* __restrict__ out_b, const float* __restrict__ h, Smem* sm)
{
    int tid = threadIdx.x, lane = tid & 31, wib = tid >> 5;
    int gw = (int)blockIdx.x * WPB + wib;

    if (tid < WPB * MAXSLOT) sm->slot[tid] = -INFINITY;

    float m0 = fmaxf(fabsf(h[tid]), fabsf(h[tid + 512]));
    m0 = wredmax(m0);
    if (lane == 0) sm->red[wib] = m0;
    __syncthreads();
    if (tid == 0) {
        float M = sm->red[0];
#pragma unroll
        for (int i = 1; i < WPB; i++) M = fmaxf(M, sm->red[i]);
        sm->bf[1] = M * (1.f / 127.f);
        sm->bf[2] = (M > 0.f) ? (127.f / M) : 0.f;
    }
    __syncthreads();
    float hs   = sm->bf[1];
    float hinv = sm->bf[2];

    if (tid < 256) sm->hq[tid] = q4(((const float4*)h)[tid], hinv);
    __syncthreads();

    const uint4* hq4 = (const uint4*)sm->hq;
    uint4 hA = hq4[lane];
    uint4 hB = hq4[lane + 32];

    float* slotp = sm->slot + wib * MAXSLOT;

#pragma unroll
    for (int b = 0; b < 2; b++) {
        int base = b * 7;
        uint4 wA[7], wB[7];
        int rr[7];
        bool okk[7];
#pragma unroll
        for (int j = 0; j < 7; j++) {
            int r = gw + (base + j) * NWARPS;
            okk[j] = (r < VOUT);
            if (!okk[j]) r = gw;
            rr[j] = r;
            const uint4* Wq = (const uint4*)(g_wq + (size_t)r * 256);
            wA[j] = __ldg(&Wq[lane]);
            wB[j] = __ldg(&Wq[lane + 32]);
        }
#pragma unroll
        for (int j = 0; j < 7; j++) {
            int acc = 0;
            acc = __dp4a((int)wA[j].x, (int)hA.x, acc);
            acc = __dp4a((int)wA[j].y, (int)hA.y, acc);
            acc = __dp4a((int)wA[j].z, (int)hA.z, acc);
            acc = __dp4a((int)wA[j].w, (int)hA.w, acc);
            acc = __dp4a((int)wB[j].x, (int)hB.x, acc);
            acc = __dp4a((int)wB[j].y, (int)hB.y, acc);
            acc = __dp4a((int)wB[j].z, (int)hB.z, acc);
            acc = __dp4a((int)wB[j].w, (int)hB.w, acc);
            acc = wredsumi(acc);
            if (lane == 0 && okk[j]) {
                int r = rr[j];
                float lg = (float)acc * (g_wscale[r] * hs) + out_b[r];
                g_logits[r] = lg;
                slotp[base + j] = lg;
            }
        }
    }

    if (lane == 0) {
        unsigned long long c0 = 0, c1 = 0, c2 = 0, c3 = 0;
#pragma unroll
        for (int n = 0; n < MAXSLOT; n++) {
            int row = gw + n * NWARPS;
            if (row < VOUT) {
                unsigned long long p = packf(slotp[n], row);
                top4_ins(c0, c1, c2, c3, p);
            }
        }
        sm->wtop[wib][0] = c0; sm->wtop[wib][1] = c1;
        sm->wtop[wib][2] = c2; sm->wtop[wib][3] = c3;
    }
    __syncthreads();

    if (wib == 0) {
        unsigned long long a0 = 0, a1 = 0, a2 = 0, a3 = 0;
        if (lane < WPB) {
            a0 = sm->wtop[lane][0]; a1 = sm->wtop[lane][1];
            a2 = sm->wtop[lane][2]; a3 = sm->wtop[lane][3];
        }
        int pos = 0;
        unsigned long long t[4];
#pragma unroll
        for (int k = 0; k < 4; k++) {
            unsigned long long head = (pos == 0) ? a0 : (pos == 1) ? a1 :
                                      (pos == 2) ? a2 : (pos == 3) ? a3 : 0ull;
            unsigned long long m = wredmaxu64(head);
            t[k] = m;
            if (head == m && pos < 4) pos++;
        }
        if (lane == 0) {
#pragma unroll
            for (int k = 0; k < 4; k++) g_ptop[blockIdx.x][k] = t[k];
            sm->bu = t[0];
        }
    }
    __syncthreads();

    {
        float m = unpack_max(sm->bu);
        float e = (tid < WPB * MAXSLOT) ? expf(sm->slot[tid] - m) : 0.f;
        e = wredsum(e);
        if (lane == 0) sm->red[wib] = e;
        __syncthreads();
        if (tid == 0) {
            float S = 0.f;
#pragma unroll
            for (int i = 0; i < 7; i++) S += sm->red[i];
            g_psum[blockIdx.x] = S;
        }
    }
}

// Phase D: warps 0-5 (named barrier): merge + recheck + tok + attn;
// warps 6-12: Whh@hn for NEXT step.
__device__ __forceinline__ void out_phase(
    const float* __restrict__ out_W, const float* __restrict__ out_b,
    const float* __restrict__ attn_W, const float* __restrict__ attn_b,
    const float* __restrict__ dec_emb, const float* __restrict__ h,
    const float* __restrict__ dec_Whh, const float* __restrict__ dec_bhh,
    Smem* sm)
{
    int tid = threadIdx.x, lane = tid & 31, wib = tid >> 5;

    if (wib >= 6 && wib < 13) {
        whh_dots(dec_Whh, dec_bhh, h, wib - 6, lane, sm);
        return;
    }
    if (wib >= 13) return;

    if (wib == 0) {
        unsigned long long c0 = 0, c1 = 0, c2 = 0, c3 = 0;
        for (int cc = lane; cc < GRID; cc += 32) {
#pragma unroll
            for (int k = 0; k < 4; k++)
                top4_ins(c0, c1, c2, c3, g_ptop[cc][k]);
        }
        int pos = 0;
        unsigned long long t[4];
#pragma unroll
        for (int k = 0; k < 4; k++) {
            unsigned long long head = (pos == 0) ? c0 : (pos == 1) ? c1 :
                                      (pos == 2) ? c2 : (pos == 3) ? c3 : 0ull;
            unsigned long long mm = wredmaxu64(head);
            t[k] = mm;
            if (head == mm && pos < 4) pos++;
        }
        float M = unpack_max(t[0]);
        float S = 0.f;
        for (int cc = lane; cc < GRID; cc += 32)
            S += g_psum[cc] * expf(unpack_max(g_ptop[cc][0]) - M);
        S = wredsum(S);
        if (lane == 0) {
#pragma unroll
            for (int k = 0; k < 4; k++) sm->top4[k] = t[k];
            sm->bf[3] = M + logf(S);
        }
    }
    BAR6();
    if (wib < 4) {
        int rk = unpack_idx(sm->top4[wib]);
        const float4* W = (const float4*)(out_W + (size_t)rk * H);
        const float4* h4 = (const float4*)h;
        float a = 0.f;
#pragma unroll 4
        for (int k = lane; k < H4; k += 32) a += dot4(W[k], h4[k]);
        a = wredsum(a);
        if (lane == 0) sm->cand[wib] = packf(a + out_b[rk], rk);
    }
    BAR6();
    unsigned long long w = sm->cand[0];
#pragma unroll
    for (int k = 1; k < 4; k++) if (sm->cand[k] > w) w = sm->cand[k];
    int tok = unpack_idx(w);
    if (wib == 0 && lane == 0) sm->tk = tok;

    if ((int)blockIdx.x < ATT) {
        int r = (int)blockIdx.x;
        if (wib == 4) {
            const float4* W  = (const float4*)(attn_W + (size_t)r * 2 * H);
            const float4* e4 = (const float4*)(dec_emb + (size_t)tok * H);
            float a = 0.f;
#pragma unroll 4
            for (int k = lane; k < H4; k += 32) a += dot4(W[k], e4[k]);
            a = wredsum(a);
            if (lane == 0) sm->bf[1] = a;
        } else if (wib == 5) {
            const float4* W  = (const float4*)(attn_W + (size_t)r * 2 * H + H);
            const float4* h4 = (const float4*)h;
            float a = 0.f;
#pragma unroll 4
            for (int k = lane; k < H4; k += 32) a += dot4(W[k], h4[k]);
            a = wredsum(a);
            if (lane == 0) sm->bf[2] = a;
        }
    }
    BAR6();
    if (wib == 4 && lane == 0 && (int)blockIdx.x < ATT)
        g_attn[blockIdx.x] = sm->bf[1] + sm->bf[2] + attn_b[blockIdx.x];
}

// ---------------- the single persistent kernel ----------------
__global__ void __launch_bounds__(BLOCK, 1) k_all(
    const int* __restrict__ tokens,
    const float* __restrict__ enc_emb,
    const float* __restrict__ enc_Wih, const float* __restrict__ enc_Whh,
    const float* __restrict__ enc_bih, const float* __restrict__ enc_bhh,
    const float* __restrict__ dec_emb,
    const float* __restrict__ attn_W, const float* __restrict__ attn_b,
    const float* __restrict__ comb_W, const float* __restrict__ comb_b,
    const float* __restrict__ dec_Wih, const float* __restrict__ dec_Whh,
    const float* __restrict__ dec_bih, const float* __restrict__ dec_bhh,
    const float* __restrict__ out_W, const float* __restrict__ out_b,
    float* __restrict__ out)
{
    __shared__ Smem sm;
    int tid = threadIdx.x;
    int wib = tid >> 5, lane = tid & 31;

    // one-time: quantize out_W to int8 with per-row scale (warp per row)
    {
        int gw = (int)blockIdx.x * WPB + wib;
#pragma unroll 1
        for (int n = 0; n < MAXSLOT; n++) {
            int r = gw + n * NWARPS;
            if (r >= VOUT) break;
            const float4* wr = (const float4*)(out_W + (size_t)r * H);
            float4 v[8];
            float mx = 0.f;
#pragma unroll
            for (int i = 0; i < 8; i++) {
                v[i] = __ldcs(&wr[lane + 32 * i]);
                mx = fmaxf(mx, fmaxf(fmaxf(fabsf(v[i].x), fabsf(v[i].y)),
                                     fmaxf(fabsf(v[i].z), fabsf(v[i].w))));
            }
            mx = wredmax(mx);
            float inv = (mx > 0.f) ? (127.f / mx) : 0.f;
            unsigned* dst = g_wq + (size_t)r * 256;
#pragma unroll
            for (int i = 0; i < 8; i++)
                dst[lane + 32 * i] = q4(v[i], inv);
            if (lane == 0) g_wscale[r] = mx * (1.f / 127.f);
        }
    }

    // one-time: precompute gix = enc_Wih @ emb[tokens] for all timesteps
    build_gix(enc_Wih, enc_emb, tokens);

    // init: h0 = 0, zero enc_T (padding columns must be 0)
    {
        int gt = (int)blockIdx.x * BLOCK + tid;
        if (gt < H) g_h[0][gt] = 0.f;
        for (int i = gt; i < H * ATTP; i += GRID * BLOCK) g_enc_T[i] = 0.f;
    }
    gsync();

    // ---- encoder: Whh-only steps using precomputed gix ----
    for (int t = 0; t < ML; t++) {
        gru_phase_enc(enc_Whh, enc_bih, enc_bhh,
                      g_h[t & 1], g_h[(t & 1) ^ 1], t, &sm);
        gsync();
    }
    // final encoder hidden in g_h[0]

    // ---- prep phase: build M (w0-6) + attn logits (w8,9) + Whh@h0 (w7,10-15) ----
    build_M(comb_W);
    if (wib == 7) whh_dots(dec_Whh, dec_bhh, g_h[0], 6, lane, &sm);
    else if (wib >= 10) whh_dots(dec_Whh, dec_bhh, g_h[0], wib - 10, lane, &sm);
    if ((int)blockIdx.x < ATT) {
        int r = (int)blockIdx.x;
        if (wib == 8) {
            const float4* W  = (const float4*)(attn_W + (size_t)r * 2 * H);
            const float4* e4 = (const float4*)dec_emb;
            float a = 0.f;
#pragma unroll 4
            for (int k = lane; k < H4; k += 32) a += dot4(W[k], e4[k]);
            a = wredsum(a);
            if (lane == 0) sm.bf[1] = a;
        } else if (wib == 9) {
            const float4* W  = (const float4*)(attn_W + (size_t)r * 2 * H + H);
            const float4* h4 = (const float4*)g_h[0];
            float a = 0.f;
#pragma unroll 4
            for (int k = lane; k < H4; k += 32) a += dot4(W[k], h4[k]);
            a = wredsum(a);
            if (lane == 0) sm.bf[2] = a;
        }
    }
    __syncthreads();
    if ((int)blockIdx.x < ATT && tid == 0)
        g_attn[blockIdx.x] = sm.bf[1] + sm.bf[2] + attn_b[blockIdx.x];
    if (tid == 0) sm.tk = 0;
    gsync();

    // ---- decoder: 4 barriers per step ----
    for (int s = 0; s < ML; s++) {
        const float* hc = g_h[s & 1];
        float* hn = g_h[(s & 1) ^ 1];

        comb_phase(comb_W, comb_b, dec_emb, &sm);              gsync();
        gru_fin_phase(dec_Wih, dec_bih, hc, hn, out, s, &sm);  gsync();
        logits_phase(out_b, hn, &sm);                          gsync();
        out_phase(out_W, out_b, attn_W, attn_b, dec_emb, hn,
                  dec_Whh, dec_bhh, &sm);                      gsync();
    }

    // final step's output (lse from last D, g_logits stable)
    {
        float lse = sm.bf[3];
        int g = (int)blockIdx.x * BLOCK + tid;
        if (g < VOUT) out[(size_t)(ML - 1) * VOUT + g] = g_logits[g] - lse;
    }
}

// ---------------- host launcher ----------------
extern "C" void kernel_launch(void* const* d_in, const int* in_sizes, int n_in,
                              void* d_out, int out_size)
{
    const int*   tokens  = (const int*)  d_in[0];
    // d_in[1] = max_length (compile-time ML=128)
    const float* enc_emb = (const float*)d_in[2];
    const float* enc_Wih = (const float*)d_in[3];
    const float* enc_Whh = (const float*)d_in[4];
    const float* enc_bih = (const float*)d_in[5];
    const float* enc_bhh = (const float*)d_in[6];
    const float* dec_emb = (const float*)d_in[7];
    const float* attn_W  = (const float*)d_in[8];
    const float* attn_b  = (const float*)d_in[9];
    const float* comb_W  = (const float*)d_in[10];
    const float* comb_b  = (const float*)d_in[11];
    const float* dec_Wih = (const float*)d_in[12];
    const float* dec_Whh = (const float*)d_in[13];
    const float* dec_bih = (const float*)d_in[14];
    const float* dec_bhh = (const float*)d_in[15];
    const float* out_W   = (const float*)d_in[16];
    const float* out_b   = (const float*)d_in[17];
    float* out = (float*)d_out;

    k_all<<<GRID, BLOCK>>>(tokens, enc_emb, enc_Wih, enc_Whh, enc_bih, enc_bhh,
                           dec_emb, attn_W, attn_b, comb_W, comb_b,
                           dec_Wih, dec_Whh, dec_bih, dec_bhh,
                           out_W, out_b, out);
}

// round 16
// speedup vs baseline: 1.0217x; 1.0217x over previous
#include <cuda_runtime.h>
#include <cuda_bf16.h>
#include <math.h>

#define H      1024
#define H4     256          // H/4
#define VOUT   32000
#define ML     128
#define ATT    129          // ML + 1
#define ATTP   160          // padded attention length (multiple of 32)
#define GRID   148
#define BLOCK  512
#define WPB    (BLOCK/32)   // 16 warps per block
#define NWARPS (GRID*WPB)   // 2368
#define MAXSLOT 14          // max rows per warp

// ---------------- device scratch (static, no allocation) ----------------
__device__ float g_h[2][H];
__device__ float g_enc_T[(size_t)H * ATTP];    // transposed encoder outputs [j][t]
__device__ float g_M[(size_t)H * ATTP];        // M[i][t] = dot(W2[i], enc_out[t])
__device__ float g_gix[(size_t)ML * 3 * H];    // gix[t][r] = enc_Wih[r] @ emb[tok_t]
__device__ float g_attn[ATT];
__device__ float g_comb[H];
__device__ float g_logits[VOUT];
__device__ float g_hmax[GRID];                 // per-CTA maxabs of its hn rows
__device__ unsigned long long g_ptop[GRID][4]; // per-CTA top-4 packed
__device__ float g_psum[GRID];                 // per-CTA sumexp wrt its own max
__device__ unsigned g_wq[(size_t)VOUT * 256];  // 32MB int8 out_W (4 int8 / uint)
__device__ float g_wscale[VOUT];               // per-row dequant scale (maxabs/127)

__device__ unsigned g_bar_count = 0;
__device__ unsigned g_bar_gen   = 0;

// ---------------- helpers ----------------
__device__ __forceinline__ float wredsum(float v) {
#pragma unroll
    for (int o = 16; o > 0; o >>= 1) v += __shfl_xor_sync(0xffffffffu, v, o);
    return v;
}
__device__ __forceinline__ int wredsumi(int v) {
#pragma unroll
    for (int o = 16; o > 0; o >>= 1) v += __shfl_xor_sync(0xffffffffu, v, o);
    return v;
}
__device__ __forceinline__ float wredmax(float v) {
#pragma unroll
    for (int o = 16; o > 0; o >>= 1) v = fmaxf(v, __shfl_xor_sync(0xffffffffu, v, o));
    return v;
}
__device__ __forceinline__ unsigned long long wredmaxu64(unsigned long long v) {
#pragma unroll
    for (int o = 16; o > 0; o >>= 1) {
        unsigned long long q = __shfl_xor_sync(0xffffffffu, v, o);
        if (q > v) v = q;
    }
    return v;
}

__device__ __forceinline__ unsigned long long packf(float v, int idx) {
    unsigned u = __float_as_uint(v);
    u = (u & 0x80000000u) ? ~u : (u | 0x80000000u);   // totally ordered float bits
    return ((unsigned long long)u << 32) | (unsigned)(~(unsigned)idx); // tie -> lowest idx
}
__device__ __forceinline__ float unpack_max(unsigned long long p) {
    unsigned u = (unsigned)(p >> 32);
    unsigned b = (u & 0x80000000u) ? (u & 0x7fffffffu) : ~u;
    return __uint_as_float(b);
}
__device__ __forceinline__ int unpack_idx(unsigned long long p) {
    return (int)(~(unsigned)(p & 0xffffffffu));
}

__device__ __forceinline__ float dot4(float4 a, float4 b) {
    return a.x * b.x + a.y * b.y + a.z * b.z + a.w * b.w;
}

__device__ __forceinline__ unsigned q4(float4 v, float inv) {
    int a = __float2int_rn(v.x * inv);
    int b = __float2int_rn(v.y * inv);
    int c = __float2int_rn(v.z * inv);
    int d = __float2int_rn(v.w * inv);
    return (unsigned)(a & 0xFF) | ((unsigned)(b & 0xFF) << 8) |
           ((unsigned)(c & 0xFF) << 16) | ((unsigned)(d & 0xFF) << 24);
}

// insert p into descending top-4
__device__ __forceinline__ void top4_ins(unsigned long long& c0, unsigned long long& c1,
                                         unsigned long long& c2, unsigned long long& c3,
                                         unsigned long long p) {
    if (p > c0)      { c3 = c2; c2 = c1; c1 = c0; c0 = p; }
    else if (p > c1) { c3 = c2; c2 = c1; c1 = p; }
    else if (p > c2) { c3 = c2; c2 = p; }
    else if (p > c3) { c3 = p; }
}

// ---------------- grid-wide barrier (local generation, acq_rel arrival) ----
__device__ __forceinline__ unsigned ld_acq(unsigned* p) {
    unsigned v;
    asm volatile("ld.acquire.gpu.u32 %0, [%1];" : "=r"(v) : "l"(p) : "memory");
    return v;
}
__device__ __forceinline__ void st_rel(unsigned* p, unsigned v) {
    asm volatile("st.release.gpu.u32 [%0], %1;" :: "l"(p), "r"(v) : "memory");
}
__device__ __forceinline__ unsigned atom_add_acqrel(unsigned* p, unsigned v) {
    unsigned old;
    asm volatile("atom.acq_rel.gpu.global.add.u32 %0, [%1], %2;"
                 : "=r"(old) : "l"(p), "r"(v) : "memory");
    return old;
}

// bgen is a per-thread local counter; all threads call gsync the same number
// of times, so the expected generation is known without loading it.
__device__ __forceinline__ void gsync(unsigned& bgen) {
    bgen++;
    __syncthreads();
    if (threadIdx.x == 0) {
        // acq_rel: release publishes this CTA's prior writes; acquire gives
        // the last arriver visibility of all CTAs' writes (transitively
        // released to waiters via st.release below).
        if (atom_add_acqrel(&g_bar_count, 1) == GRID - 1) {
            g_bar_count = 0;                 // ordered before gen by release
            st_rel(&g_bar_gen, bgen);
        } else {
            while (ld_acq(&g_bar_gen) != bgen) { }
        }
    }
    __syncthreads();
}

#define BAR6() asm volatile("bar.sync 1, 192;" ::: "memory")

// ---------------- shared-memory layout ----------------
struct Smem {
    float e[ATTP];                // attention softmax weights (zero-padded)
    float slot[WPB * MAXSLOT];    // raw logits per warp slot
    float red[WPB];               // warp-level reduction scratch
    float gh[8][4];               // Whh@h gate sums (+bhh), from prev D / prep
    float gi[8][4];               // hi-half partials exchange (B phase / encoder)
    float ca[8];                  // comb hi partials (A) / |hnew| (B)
    unsigned hq[256];             // quantized h (4 int8 per uint)
    unsigned long long wtop[WPB][4];
    unsigned long long top4[4];
    unsigned long long cand[4];
    float bf[4];                  // scalar broadcasts (bf[3] = lse for delayed write)
    unsigned long long bu;
    int tk;                       // CTA-local current token
};

// ---------------- phases ----------------

// one-time: gix[t][r] = dot(enc_Wih[r], enc_emb[tokens[t]]) for all t, r.
__device__ __forceinline__ void build_gix(
    const float* __restrict__ enc_Wih, const float* __restrict__ enc_emb,
    const int* __restrict__ tokens)
{
    int cta = (int)blockIdx.x;
    if (cta >= 144) return;
    int gtg = cta & 7;            // token group
    int j   = cta >> 3;           // 0..17: row residue
    int wib = threadIdx.x >> 5;
    int lane = threadIdx.x & 31;
    int t = gtg * 16 + wib;       // token 0..127

    const float4* e4 = (const float4*)(enc_emb + (size_t)tokens[t] * H);
    float4 ev[8];
#pragma unroll
    for (int i = 0; i < 8; i++) ev[i] = e4[lane + 32 * i];

    float* gx = g_gix + (size_t)t * (3 * H);

#pragma unroll 1
    for (int r0 = j; r0 < 3 * H; r0 += 72) {
        int r1 = r0 + 18, r2 = r0 + 36, r3 = r0 + 54;
        bool b1 = r1 < 3 * H, b2 = r2 < 3 * H, b3 = r3 < 3 * H;
        const float4* W0 = (const float4*)(enc_Wih + (size_t)r0 * H);
        const float4* W1 = (const float4*)(enc_Wih + (size_t)(b1 ? r1 : r0) * H);
        const float4* W2 = (const float4*)(enc_Wih + (size_t)(b2 ? r2 : r0) * H);
        const float4* W3 = (const float4*)(enc_Wih + (size_t)(b3 ? r3 : r0) * H);
        float a0 = 0.f, a1 = 0.f, a2 = 0.f, a3 = 0.f;
#pragma unroll
        for (int i = 0; i < 8; i++) {
            float4 w0 = W0[lane + 32 * i];
            float4 w1 = W1[lane + 32 * i];
            float4 w2 = W2[lane + 32 * i];
            float4 w3 = W3[lane + 32 * i];
            a0 += dot4(w0, ev[i]);
            a1 += dot4(w1, ev[i]);
            a2 += dot4(w2, ev[i]);
            a3 += dot4(w3, ev[i]);
        }
        a0 = wredsum(a0);
        a1 = wredsum(a1);
        a2 = wredsum(a2);
        a3 = wredsum(a3);
        if (lane == 0) {
            gx[r0] = a0;
            if (b1) gx[r1] = a1;
            if (b2) gx[r2] = a2;
            if (b3) gx[r3] = a3;
        }
    }
}

// Encoder GRU step using precomputed gix: Whh@h k-split across warp pairs.
__device__ __forceinline__ void gru_phase_enc(
    const float* __restrict__ Whh,
    const float* __restrict__ bih, const float* __restrict__ bhh,
    const float* __restrict__ h, float* __restrict__ ho, int t, Smem* sm)
{
    int wib = threadIdx.x >> 5;
    int lane = threadIdx.x & 31;
    int wp = wib & 7;
    bool lo = (wib < 7);
    bool hi = (wib >= 8 && wib < 15);
    int row = wp * GRID + (int)blockIdx.x;
    bool act = (lo || hi) && row < H;

    float hr = 0.f, hz = 0.f, hn = 0.f;
    if (act) {
        const float4* h4 = (const float4*)h;
        const float4* W0 = (const float4*)(Whh + (size_t)row * H);
        const float4* W1 = (const float4*)(Whh + (size_t)(row + H) * H);
        const float4* W2 = (const float4*)(Whh + (size_t)(row + 2 * H) * H);
        int k0 = lo ? 0 : 128;
#pragma unroll 4
        for (int k = k0 + lane; k < k0 + 128; k += 32) {
            float4 hv = h4[k];
            hr += dot4(W0[k], hv);
            hz += dot4(W1[k], hv);
            hn += dot4(W2[k], hv);
        }
        hr = wredsum(hr); hz = wredsum(hz); hn = wredsum(hn);
        if (hi && lane == 0) {
            sm->gi[wp][0] = hr; sm->gi[wp][1] = hz; sm->gi[wp][2] = hn;
        }
    }
    __syncthreads();
    if (act && lo && lane == 0) {
        const float* gx = g_gix + (size_t)t * (3 * H);
        float ir  = gx[row]         + bih[row];
        float iz  = gx[row + H]     + bih[row + H];
        float inn = gx[row + 2 * H] + bih[row + 2 * H];
        float HR = hr + sm->gi[wp][0] + bhh[row];
        float HZ = hz + sm->gi[wp][1] + bhh[row + H];
        float HN = hn + sm->gi[wp][2] + bhh[row + 2 * H];
        float r = 1.f / (1.f + expf(-(ir + HR)));
        float z = 1.f / (1.f + expf(-(iz + HZ)));
        float n = tanhf(inn + r * HN);
        float hnew = (1.f - z) * n + z * h[row];
        ho[row] = hnew;
        g_enc_T[(size_t)row * ATTP + t] = hnew;
    }
}

// one-time after encoder: M[i][t] = dot(comb_W[i, H:2H], enc_out[t])
__device__ __forceinline__ void build_M(const float* __restrict__ comb_W)
{
    int wib = threadIdx.x >> 5;
    int lane = threadIdx.x & 31;
    if (wib >= 7) return;
    int row = wib * GRID + (int)blockIdx.x;
    if (row >= H) return;

    const float4* W2 = (const float4*)(comb_W + (size_t)row * 2 * H + H);
    float a0 = 0.f, a1 = 0.f, a2 = 0.f, a3 = 0.f, a4 = 0.f;
#pragma unroll 2
    for (int j4 = 0; j4 < H4; j4++) {
        float4 w = W2[j4];
        const float* E = g_enc_T + (size_t)(j4 * 4) * ATTP + lane;
#pragma unroll
        for (int c = 0; c < 4; c++) {
            float wc = (c == 0) ? w.x : (c == 1) ? w.y : (c == 2) ? w.z : w.w;
            const float* Ec = E + (size_t)c * ATTP;
            a0 += wc * Ec[0];
            a1 += wc * Ec[32];
            a2 += wc * Ec[64];
            a3 += wc * Ec[96];
            a4 += wc * Ec[128];
        }
    }
    float* Mr = g_M + (size_t)row * ATTP;
    Mr[lane]       = a0;
    Mr[lane + 32]  = a1;
    Mr[lane + 64]  = a2;
    Mr[lane + 96]  = a3;
    Mr[lane + 128] = a4;
}

// Whh@h gate sums for row wp (full k), writes sm->gh[wp] (+bhh)
__device__ __forceinline__ void whh_dots(
    const float* __restrict__ Whh, const float* __restrict__ bhh,
    const float* __restrict__ h, int wp, int lane, Smem* sm)
{
    int row = wp * GRID + (int)blockIdx.x;
    if (row >= H) return;
    const float4* h4 = (const float4*)h;
    const float4* W0 = (const float4*)(Whh + (size_t)row * H);
    const float4* W1 = (const float4*)(Whh + (size_t)(row + H) * H);
    const float4* W2 = (const float4*)(Whh + (size_t)(row + 2 * H) * H);
    float hr = 0.f, hz = 0.f, hn = 0.f;
#pragma unroll 4
    for (int k = lane; k < H4; k += 32) {
        float4 hv = h4[k];
        hr += dot4(W0[k], hv);
        hz += dot4(W1[k], hv);
        hn += dot4(W2[k], hv);
    }
    hr = wredsum(hr); hz = wredsum(hz); hn = wredsum(hn);
    if (lane == 0) {
        sm->gh[wp][0] = hr + bhh[row];
        sm->gh[wp][1] = hz + bhh[row + H];
        sm->gh[wp][2] = hn + bhh[row + 2 * H];
    }
}

// Phase A: softmax (w15) + comb rows k-split across warp pairs (w0-6 / w8-14).
__device__ __forceinline__ void comb_phase(
    const float* __restrict__ comb_W, const float* __restrict__ comb_b,
    const float* __restrict__ dec_emb, Smem* sm)
{
    int wib = threadIdx.x >> 5;
    int lane = threadIdx.x & 31;
    int tok = sm->tk;

    if (wib == 15) {
        float v[5];
        float mx = -INFINITY;
#pragma unroll
        for (int k = 0; k < 5; k++) {
            int idx = lane + 32 * k;
            v[k] = (idx < ATT) ? g_attn[idx] : -INFINITY;
            mx = fmaxf(mx, v[k]);
        }
        mx = wredmax(mx);
        float s = 0.f;
#pragma unroll
        for (int k = 0; k < 5; k++) {
            int idx = lane + 32 * k;
            float e = (idx < ATT) ? expf(v[k] - mx) : 0.f;
            sm->e[idx] = e;
            s += e;
        }
        s = wredsum(s);
        if (lane == 0) sm->bf[0] = 1.f / s;
    }

    int wp = wib & 7;
    bool lo = (wib < 7);
    bool hi = (wib >= 8 && wib < 15);
    int row = wp * GRID + (int)blockIdx.x;
    bool act = (lo || hi) && row < H;

    float a = 0.f;
    if (act) {
        const float4* W  = (const float4*)(comb_W + (size_t)row * 2 * H);
        const float4* e4 = (const float4*)(dec_emb + (size_t)tok * H);
        int k0 = lo ? 0 : 128;
#pragma unroll 4
        for (int k = k0 + lane; k < k0 + 128; k += 32) a += dot4(W[k], e4[k]);
        if (hi) {
            a = wredsum(a);
            if (lane == 0) sm->ca[wp] = a;
        }
    }
    __syncthreads();
    if (act && lo) {
        const float* Mr = g_M + (size_t)row * ATTP;
        float b = 0.f;
#pragma unroll
        for (int k = 0; k < 5; k++) {
            int t = lane + 32 * k;
            b += sm->e[t] * Mr[t];
        }
        float tot = a + b * sm->bf[0];
        tot = wredsum(tot);
        if (lane == 0)
            g_comb[row] = fmaxf(tot + sm->ca[wp] + comb_b[row], 0.f);
    }
}

// Phase B: gru finish — Wih@comb k-split + gates; warps 7,15 write prev output;
// epilogue reduces this CTA's |hnew| values into g_hmax[cta].
__device__ __forceinline__ void gru_fin_phase(
    const float* __restrict__ dec_Wih, const float* __restrict__ dec_bih,
    const float* __restrict__ hc, float* __restrict__ hn_out,
    float* __restrict__ out, int step, Smem* sm)
{
    int wib = threadIdx.x >> 5;
    int lane = threadIdx.x & 31;
    int wp = wib & 7;
    bool lo = (wib < 7);
    bool hi = (wib >= 8 && wib < 15);
    int row = wp * GRID + (int)blockIdx.x;
    bool act = (lo || hi) && row < H;

    if (threadIdx.x < 8) sm->ca[threadIdx.x] = 0.f;   // |hnew| slots

    float ir = 0.f, iz = 0.f, inn = 0.f;
    if (act) {
        const float4* x4 = (const float4*)g_comb;
        const float4* W0 = (const float4*)(dec_Wih + (size_t)row * H);
        const float4* W1 = (const float4*)(dec_Wih + (size_t)(row + H) * H);
        const float4* W2 = (const float4*)(dec_Wih + (size_t)(row + 2 * H) * H);
        int k0 = lo ? 0 : 128;
#pragma unroll 4
        for (int k = k0 + lane; k < k0 + 128; k += 32) {
            float4 xv = x4[k];
            ir  += dot4(W0[k], xv);
            iz  += dot4(W1[k], xv);
            inn += dot4(W2[k], xv);
        }
        ir = wredsum(ir); iz = wredsum(iz); inn = wredsum(inn);
        if (hi && lane == 0) {
            sm->gi[wp][0] = ir; sm->gi[wp][1] = iz; sm->gi[wp][2] = inn;
        }
    } else if ((wib == 7 || wib == 15) && step > 0) {
        float lse = sm->bf[3];
        int wt = (wib == 7 ? lane : 32 + lane);
        for (int g = (int)blockIdx.x * 64 + wt; g < VOUT; g += GRID * 64)
            out[(size_t)(step - 1) * VOUT + g] = g_logits[g] - lse;
    }
    __syncthreads();
    if (act && lo && lane == 0) {
        float IR = ir + sm->gi[wp][0] + dec_bih[row];
        float IZ = iz + sm->gi[wp][1] + dec_bih[row + H];
        float IN = inn + sm->gi[wp][2] + dec_bih[row + 2 * H];
        float hr = sm->gh[wp][0];
        float hz = sm->gh[wp][1];
        float hn = sm->gh[wp][2];
        float r = 1.f / (1.f + expf(-(IR + hr)));
        float z = 1.f / (1.f + expf(-(IZ + hz)));
        float n = tanhf(IN + r * hn);
        float hnew = (1.f - z) * n + z * hc[row];
        hn_out[row] = hnew;
        sm->ca[wp] = fabsf(hnew);
    }
    __syncthreads();
    if (wib == 0) {
        float m = (lane < 8) ? sm->ca[lane] : 0.f;
        m = wredmax(m);
        if (lane == 0) g_hmax[blockIdx.x] = m;
    }
}

// Phase C: logits GEMV on int8 weights; h scale from g_hmax (148-value reduce)
__device__ __forceinline__ void logits_phase(
    const float* __restrict__ out_b, const float* __restrict__ h, Smem* sm)
{
    int tid = threadIdx.x, lane = tid & 31, wib = tid >> 5;
    int gw = (int)blockIdx.x * WPB + wib;

    if (tid < WPB * MAXSLOT) sm->slot[tid] = -INFINITY;

    if (wib == 0) {               // global maxabs from per-CTA partials
        float m = 0.f;
#pragma unroll
        for (int k = 0; k < 5; k++) {
            int idx = lane + 32 * k;
            if (idx < GRID) m = fmaxf(m, g_hmax[idx]);
        }
        m = wredmax(m);
        if (lane == 0) {
            sm->bf[1] = m * (1.f / 127.f);
            sm->bf[2] = (m > 0.f) ? (127.f / m) : 0.f;
        }
    }
    __syncthreads();
    float hs   = sm->bf[1];
    float hinv = sm->bf[2];

    if (tid < 256) sm->hq[tid] = q4(((const float4*)h)[tid], hinv);
    __syncthreads();

    const uint4* hq4 = (const uint4*)sm->hq;
    uint4 hA = hq4[lane];
    uint4 hB = hq4[lane + 32];

    float* slotp = sm->slot + wib * MAXSLOT;

#pragma unroll
    for (int b = 0; b < 2; b++) {
        int base = b * 7;
        uint4 wA[7], wB[7];
        int rr[7];
        bool okk[7];
#pragma unroll
        for (int j = 0; j < 7; j++) {
            int r = gw + (base + j) * NWARPS;
            okk[j] = (r < VOUT);
            if (!okk[j]) r = gw;
            rr[j] = r;
            const uint4* Wq = (const uint4*)(g_wq + (size_t)r * 256);
            wA[j] = __ldg(&Wq[lane]);
            wB[j] = __ldg(&Wq[lane + 32]);
        }
#pragma unroll
        for (int j = 0; j < 7; j++) {
            int acc = 0;
            acc = __dp4a((int)wA[j].x, (int)hA.x, acc);
            acc = __dp4a((int)wA[j].y, (int)hA.y, acc);
            acc = __dp4a((int)wA[j].z, (int)hA.z, acc);
            acc = __dp4a((int)wA[j].w, (int)hA.w, acc);
            acc = __dp4a((int)wB[j].x, (int)hB.x, acc);
            acc = __dp4a((int)wB[j].y, (int)hB.y, acc);
            acc = __dp4a((int)wB[j].z, (int)hB.z, acc);
            acc = __dp4a((int)wB[j].w, (int)hB.w, acc);
            acc = wredsumi(acc);
            if (lane == 0 && okk[j]) {
                int r = rr[j];
                float lg = (float)acc * (g_wscale[r] * hs) + out_b[r];
                g_logits[r] = lg;
                slotp[base + j] = lg;
            }
        }
    }

    if (lane == 0) {
        unsigned long long c0 = 0, c1 = 0, c2 = 0, c3 = 0;
#pragma unroll
        for (int n = 0; n < MAXSLOT; n++) {
            int row = gw + n * NWARPS;
            if (row < VOUT) {
                unsigned long long p = packf(slotp[n], row);
                top4_ins(c0, c1, c2, c3, p);
            }
        }
        sm->wtop[wib][0] = c0; sm->wtop[wib][1] = c1;
        sm->wtop[wib][2] = c2; sm->wtop[wib][3] = c3;
    }
    __syncthreads();

    if (wib == 0) {
        unsigned long long a0 = 0, a1 = 0, a2 = 0, a3 = 0;
        if (lane < WPB) {
            a0 = sm->wtop[lane][0]; a1 = sm->wtop[lane][1];
            a2 = sm->wtop[lane][2]; a3 = sm->wtop[lane][3];
        }
        int pos = 0;
        unsigned long long t[4];
#pragma unroll
        for (int k = 0; k < 4; k++) {
            unsigned long long head = (pos == 0) ? a0 : (pos == 1) ? a1 :
                                      (pos == 2) ? a2 : (pos == 3) ? a3 : 0ull;
            unsigned long long m = wredmaxu64(head);
            t[k] = m;
            if (head == m && pos < 4) pos++;
        }
        if (lane == 0) {
#pragma unroll
            for (int k = 0; k < 4; k++) g_ptop[blockIdx.x][k] = t[k];
            sm->bu = t[0];
        }
    }
    __syncthreads();

    {
        float m = unpack_max(sm->bu);
        float e = (tid < WPB * MAXSLOT) ? expf(sm->slot[tid] - m) : 0.f;
        e = wredsum(e);
        if (lane == 0) sm->red[wib] = e;
        __syncthreads();
        if (tid == 0) {
            float S = 0.f;
#pragma unroll
            for (int i = 0; i < 7; i++) S += sm->red[i];
            g_psum[blockIdx.x] = S;
        }
    }
}

// Phase D: warps 0-5 (named barrier): merge + recheck + tok + attn;
// warps 6-12: Whh@hn for NEXT step.
__device__ __forceinline__ void out_phase(
    const float* __restrict__ out_W, const float* __restrict__ out_b,
    const float* __restrict__ attn_W, const float* __restrict__ attn_b,
    const float* __restrict__ dec_emb, const float* __restrict__ h,
    const float* __restrict__ dec_Whh, const float* __restrict__ dec_bhh,
    Smem* sm)
{
    int tid = threadIdx.x, lane = tid & 31, wib = tid >> 5;

    if (wib >= 6 && wib < 13) {
        whh_dots(dec_Whh, dec_bhh, h, wib - 6, lane, sm);
        return;
    }
    if (wib >= 13) return;

    if (wib == 0) {
        unsigned long long c0 = 0, c1 = 0, c2 = 0, c3 = 0;
        for (int cc = lane; cc < GRID; cc += 32) {
#pragma unroll
            for (int k = 0; k < 4; k++)
                top4_ins(c0, c1, c2, c3, g_ptop[cc][k]);
        }
        int pos = 0;
        unsigned long long t[4];
#pragma unroll
        for (int k = 0; k < 4; k++) {
            unsigned long long head = (pos == 0) ? c0 : (pos == 1) ? c1 :
                                      (pos == 2) ? c2 : (pos == 3) ? c3 : 0ull;
            unsigned long long mm = wredmaxu64(head);
            t[k] = mm;
            if (head == mm && pos < 4) pos++;
        }
        float M = unpack_max(t[0]);
        float S = 0.f;
        for (int cc = lane; cc < GRID; cc += 32)
            S += g_psum[cc] * expf(unpack_max(g_ptop[cc][0]) - M);
        S = wredsum(S);
        if (lane == 0) {
#pragma unroll
            for (int k = 0; k < 4; k++) sm->top4[k] = t[k];
            sm->bf[3] = M + logf(S);
        }
    }
    BAR6();
    if (wib < 4) {
        int rk = unpack_idx(sm->top4[wib]);
        const float4* W = (const float4*)(out_W + (size_t)rk * H);
        const float4* h4 = (const float4*)h;
        float a = 0.f;
#pragma unroll 4
        for (int k = lane; k < H4; k += 32) a += dot4(W[k], h4[k]);
        a = wredsum(a);
        if (lane == 0) sm->cand[wib] = packf(a + out_b[rk], rk);
    }
    BAR6();
    unsigned long long w = sm->cand[0];
#pragma unroll
    for (int k = 1; k < 4; k++) if (sm->cand[k] > w) w = sm->cand[k];
    int tok = unpack_idx(w);
    if (wib == 0 && lane == 0) sm->tk = tok;

    if ((int)blockIdx.x < ATT) {
        int r = (int)blockIdx.x;
        if (wib == 4) {
            const float4* W  = (const float4*)(attn_W + (size_t)r * 2 * H);
            const float4* e4 = (const float4*)(dec_emb + (size_t)tok * H);
            float a = 0.f;
#pragma unroll 4
            for (int k = lane; k < H4; k += 32) a += dot4(W[k], e4[k]);
            a = wredsum(a);
            if (lane == 0) sm->bf[1] = a;
        } else if (wib == 5) {
            const float4* W  = (const float4*)(attn_W + (size_t)r * 2 * H + H);
            const float4* h4 = (const float4*)h;
            float a = 0.f;
#pragma unroll 4
            for (int k = lane; k < H4; k += 32) a += dot4(W[k], h4[k]);
            a = wredsum(a);
            if (lane == 0) sm->bf[2] = a;
        }
    }
    BAR6();
    if (wib == 4 && lane == 0 && (int)blockIdx.x < ATT)
        g_attn[blockIdx.x] = sm->bf[1] + sm->bf[2] + attn_b[blockIdx.x];
}

// ---------------- the single persistent kernel ----------------
__global__ void __launch_bounds__(BLOCK, 1) k_all(
    const int* __restrict__ tokens,
    const float* __restrict__ enc_emb,
    const float* __restrict__ enc_Wih, const float* __restrict__ enc_Whh,
    const float* __restrict__ enc_bih, const float* __restrict__ enc_bhh,
    const float* __restrict__ dec_emb,
    const float* __restrict__ attn_W, const float* __restrict__ attn_b,
    const float* __restrict__ comb_W, const float* __restrict__ comb_b,
    const float* __restrict__ dec_Wih, const float* __restrict__ dec_Whh,
    const float* __restrict__ dec_bih, const float* __restrict__ dec_bhh,
    const float* __restrict__ out_W, const float* __restrict__ out_b,
    float* __restrict__ out)
{
    __shared__ Smem sm;
    int tid = threadIdx.x;
    int wib = tid >> 5, lane = tid & 31;
    unsigned bgen = 0;

    // one-time: quantize out_W to int8 with per-row scale (warp per row)
    {
        int gw = (int)blockIdx.x * WPB + wib;
#pragma unroll 1
        for (int n = 0; n < MAXSLOT; n++) {
            int r = gw + n * NWARPS;
            if (r >= VOUT) break;
            const float4* wr = (const float4*)(out_W + (size_t)r * H);
            float4 v[8];
            float mx = 0.f;
#pragma unroll
            for (int i = 0; i < 8; i++) {
                v[i] = __ldcs(&wr[lane + 32 * i]);
                mx = fmaxf(mx, fmaxf(fmaxf(fabsf(v[i].x), fabsf(v[i].y)),
                                     fmaxf(fabsf(v[i].z), fabsf(v[i].w))));
            }
            mx = wredmax(mx);
            float inv = (mx > 0.f) ? (127.f / mx) : 0.f;
            unsigned* dst = g_wq + (size_t)r * 256;
#pragma unroll
            for (int i = 0; i < 8; i++)
                dst[lane + 32 * i] = q4(v[i], inv);
            if (lane == 0) g_wscale[r] = mx * (1.f / 127.f);
        }
    }

    // one-time: precompute gix = enc_Wih @ emb[tokens] for all timesteps
    build_gix(enc_Wih, enc_emb, tokens);

    // init: h0 = 0, zero enc_T (padding columns must be 0)
    {
        int gt = (int)blockIdx.x * BLOCK + tid;
        if (gt < H) g_h[0][gt] = 0.f;
        for (int i = gt; i < H * ATTP; i += GRID * BLOCK) g_enc_T[i] = 0.f;
    }
    gsync(bgen);

    // ---- encoder: Whh-only steps using precomputed gix ----
    for (int t = 0; t < ML; t++) {
        gru_phase_enc(enc_Whh, enc_bih, enc_bhh,
                      g_h[t & 1], g_h[(t & 1) ^ 1], t, &sm);
        gsync(bgen);
    }
    // final encoder hidden in g_h[0]

    // ---- prep phase: build M (w0-6) + attn logits (w8,9) + Whh@h0 (w7,10-15) ----
    build_M(comb_W);
    if (wib == 7) whh_dots(dec_Whh, dec_bhh, g_h[0], 6, lane, &sm);
    else if (wib >= 10) whh_dots(dec_Whh, dec_bhh, g_h[0], wib - 10, lane, &sm);
    if ((int)blockIdx.x < ATT) {
        int r = (int)blockIdx.x;
        if (wib == 8) {
            const float4* W  = (const float4*)(attn_W + (size_t)r * 2 * H);
            const float4* e4 = (const float4*)dec_emb;
            float a = 0.f;
#pragma unroll 4
            for (int k = lane; k < H4; k += 32) a += dot4(W[k], e4[k]);
            a = wredsum(a);
            if (lane == 0) sm.bf[1] = a;
        } else if (wib == 9) {
            const float4* W  = (const float4*)(attn_W + (size_t)r * 2 * H + H);
            const float4* h4 = (const float4*)g_h[0];
            float a = 0.f;
#pragma unroll 4
            for (int k = lane; k < H4; k += 32) a += dot4(W[k], h4[k]);
            a = wredsum(a);
            if (lane == 0) sm.bf[2] = a;
        }
    }
    __syncthreads();
    if ((int)blockIdx.x < ATT && tid == 0)
        g_attn[blockIdx.x] = sm.bf[1] + sm.bf[2] + attn_b[blockIdx.x];
    if (tid == 0) sm.tk = 0;
    gsync(bgen);

    // ---- decoder: 4 barriers per step ----
    for (int s = 0; s < ML; s++) {
        const float* hc = g_h[s & 1];
        float* hn = g_h[(s & 1) ^ 1];

        comb_phase(comb_W, comb_b, dec_emb, &sm);              gsync(bgen);
        gru_fin_phase(dec_Wih, dec_bih, hc, hn, out, s, &sm);  gsync(bgen);
        logits_phase(out_b, hn, &sm);                          gsync(bgen);
        out_phase(out_W, out_b, attn_W, attn_b, dec_emb, hn,
                  dec_Whh, dec_bhh, &sm);                      gsync(bgen);
    }

    // final step's output (lse from last D, g_logits stable)
    {
        float lse = sm.bf[3];
        int g = (int)blockIdx.x * BLOCK + tid;
        if (g < VOUT) out[(size_t)(ML - 1) * VOUT + g] = g_logits[g] - lse;
    }
}

// ---------------- host launcher ----------------
extern "C" void kernel_launch(void* const* d_in, const int* in_sizes, int n_in,
                              void* d_out, int out_size)
{
    const int*   tokens  = (const int*)  d_in[0];
    // d_in[1] = max_length (compile-time ML=128)
    const float* enc_emb = (const float*)d_in[2];
    const float* enc_Wih = (const float*)d_in[3];
    const float* enc_Whh = (const float*)d_in[4];
    const float* enc_bih = (const float*)d_in[5];
    const float* enc_bhh = (const float*)d_in[6];
    const float* dec_emb = (const float*)d_in[7];
    const float* attn_W  = (const float*)d_in[8];
    const float* attn_b  = (const float*)d_in[9];
    const float* comb_W  = (const float*)d_in[10];
    const float* comb_b  = (const float*)d_in[11];
    const float* dec_Wih = (const float*)d_in[12];
    const float* dec_Whh = (const float*)d_in[13];
    const float* dec_bih = (const float*)d_in[14];
    const float* dec_bhh = (const float*)d_in[15];
    const float* out_W   = (const float*)d_in[16];
    const float* out_b   = (const float*)d_in[17];
    float* out = (float*)d_out;

    k_all<<<GRID, BLOCK>>>(tokens, enc_emb, enc_Wih, enc_Whh, enc_bih, enc_bhh,
                           dec_emb, attn_W, attn_b, comb_W, comb_b,
                           dec_Wih, dec_Whh, dec_bih, dec_bhh,
                           out_W, out_b, out);
}

// round 17
// speedup vs baseline: 1.1850x; 1.1598x over previous
#include <cuda_runtime.h>
#include <cuda_bf16.h>
#include <math.h>

#define H      1024
#define H4     256          // H/4
#define VOUT   32000
#define ML     128
#define ATT    129          // ML + 1
#define ATTP   160          // padded attention length (multiple of 32)
#define GRID   148
#define BLOCK  512
#define WPB    (BLOCK/32)   // 16 warps per block
#define NWARPS (GRID*WPB)   // 2368
#define MAXSLOT 14          // max rows per warp

// ---------------- device scratch (static, no allocation) ----------------
__device__ float g_h[2][H];
__device__ float g_enc_T[(size_t)H * ATTP];    // transposed encoder outputs [j][t]
__device__ float g_M[(size_t)H * ATTP];        // M[i][t] = dot(W2[i], enc_out[t])
__device__ float g_gix[(size_t)ML * 3 * H];    // gix[t][r] = enc_Wih[r] @ emb[tok_t]
__device__ float g_attn[ATT];
__device__ float g_comb[H];
__device__ float g_logits[VOUT];
__device__ float g_hmax[GRID];                 // per-CTA maxabs of its hn rows
__device__ unsigned long long g_ptop1[GRID];   // per-CTA int8 top-1 packed (lse ref)
__device__ unsigned long long g_pfix[GRID][2]; // per-CTA fp32-rechecked top-2 packed
__device__ float g_psum[GRID];                 // per-CTA sumexp wrt its own max
__device__ unsigned g_wq[(size_t)VOUT * 256];  // 32MB int8 out_W (4 int8 / uint)
__device__ float g_wscale[VOUT];               // per-row dequant scale (maxabs/127)

__device__ unsigned g_bar_count = 0;
__device__ unsigned g_bar_gen   = 0;

// ---------------- helpers ----------------
__device__ __forceinline__ float wredsum(float v) {
#pragma unroll
    for (int o = 16; o > 0; o >>= 1) v += __shfl_xor_sync(0xffffffffu, v, o);
    return v;
}
__device__ __forceinline__ int wredsumi(int v) {
#pragma unroll
    for (int o = 16; o > 0; o >>= 1) v += __shfl_xor_sync(0xffffffffu, v, o);
    return v;
}
__device__ __forceinline__ float wredmax(float v) {
#pragma unroll
    for (int o = 16; o > 0; o >>= 1) v = fmaxf(v, __shfl_xor_sync(0xffffffffu, v, o));
    return v;
}
__device__ __forceinline__ unsigned long long wredmaxu64(unsigned long long v) {
#pragma unroll
    for (int o = 16; o > 0; o >>= 1) {
        unsigned long long q = __shfl_xor_sync(0xffffffffu, v, o);
        if (q > v) v = q;
    }
    return v;
}

__device__ __forceinline__ unsigned long long packf(float v, int idx) {
    unsigned u = __float_as_uint(v);
    u = (u & 0x80000000u) ? ~u : (u | 0x80000000u);   // totally ordered float bits
    return ((unsigned long long)u << 32) | (unsigned)(~(unsigned)idx); // tie -> lowest idx
}
__device__ __forceinline__ float unpack_max(unsigned long long p) {
    unsigned u = (unsigned)(p >> 32);
    unsigned b = (u & 0x80000000u) ? (u & 0x7fffffffu) : ~u;
    return __uint_as_float(b);
}
__device__ __forceinline__ int unpack_idx(unsigned long long p) {
    return (int)(~(unsigned)(p & 0xffffffffu));
}

__device__ __forceinline__ float dot4(float4 a, float4 b) {
    return a.x * b.x + a.y * b.y + a.z * b.z + a.w * b.w;
}

__device__ __forceinline__ unsigned q4(float4 v, float inv) {
    int a = __float2int_rn(v.x * inv);
    int b = __float2int_rn(v.y * inv);
    int c = __float2int_rn(v.z * inv);
    int d = __float2int_rn(v.w * inv);
    return (unsigned)(a & 0xFF) | ((unsigned)(b & 0xFF) << 8) |
           ((unsigned)(c & 0xFF) << 16) | ((unsigned)(d & 0xFF) << 24);
}

// insert p into descending top-4
__device__ __forceinline__ void top4_ins(unsigned long long& c0, unsigned long long& c1,
                                         unsigned long long& c2, unsigned long long& c3,
                                         unsigned long long p) {
    if (p > c0)      { c3 = c2; c2 = c1; c1 = c0; c0 = p; }
    else if (p > c1) { c3 = c2; c2 = c1; c1 = p; }
    else if (p > c2) { c3 = c2; c2 = p; }
    else if (p > c3) { c3 = p; }
}

// ---------------- grid-wide barrier (local generation, acq_rel arrival) ----
__device__ __forceinline__ unsigned ld_acq(unsigned* p) {
    unsigned v;
    asm volatile("ld.acquire.gpu.u32 %0, [%1];" : "=r"(v) : "l"(p) : "memory");
    return v;
}
__device__ __forceinline__ void st_rel(unsigned* p, unsigned v) {
    asm volatile("st.release.gpu.u32 [%0], %1;" :: "l"(p), "r"(v) : "memory");
}
__device__ __forceinline__ unsigned atom_add_acqrel(unsigned* p, unsigned v) {
    unsigned old;
    asm volatile("atom.acq_rel.gpu.global.add.u32 %0, [%1], %2;"
                 : "=r"(old) : "l"(p), "r"(v) : "memory");
    return old;
}

__device__ __forceinline__ void gsync(unsigned& bgen) {
    bgen++;
    __syncthreads();
    if (threadIdx.x == 0) {
        if (atom_add_acqrel(&g_bar_count, 1) == GRID - 1) {
            g_bar_count = 0;
            st_rel(&g_bar_gen, bgen);
        } else {
            while (ld_acq(&g_bar_gen) != bgen) { }
        }
    }
    __syncthreads();
}

#define BAR6() asm volatile("bar.sync 1, 192;" ::: "memory")

// ---------------- shared-memory layout ----------------
struct Smem {
    float e[ATTP];                // attention softmax weights (zero-padded)
    float slot[WPB * MAXSLOT];    // raw logits per warp slot
    float red[WPB];               // warp-level reduction scratch
    float gh[8][4];               // Whh@h gate sums (+bhh), from prev D / prep
    float gi[8][4];               // hi-half partials exchange (B phase / encoder)
    float ca[8];                  // comb hi partials (A) / |hnew| (B)
    unsigned hq[256];             // quantized h (4 int8 per uint)
    unsigned long long wtop[WPB][4];
    unsigned long long top4[4];   // CTA int8 top-4 (for in-C recheck)
    float bf[4];                  // scalar broadcasts (bf[3] = lse for delayed write)
    unsigned long long bu;
    int tk;                       // CTA-local current token
};

// ---------------- phases ----------------

// one-time: gix[t][r] = dot(enc_Wih[r], enc_emb[tokens[t]]) for all t, r.
__device__ __forceinline__ void build_gix(
    const float* __restrict__ enc_Wih, const float* __restrict__ enc_emb,
    const int* __restrict__ tokens)
{
    int cta = (int)blockIdx.x;
    if (cta >= 144) return;
    int gtg = cta & 7;            // token group
    int j   = cta >> 3;           // 0..17: row residue
    int wib = threadIdx.x >> 5;
    int lane = threadIdx.x & 31;
    int t = gtg * 16 + wib;       // token 0..127

    const float4* e4 = (const float4*)(enc_emb + (size_t)tokens[t] * H);
    float4 ev[8];
#pragma unroll
    for (int i = 0; i < 8; i++) ev[i] = e4[lane + 32 * i];

    float* gx = g_gix + (size_t)t * (3 * H);

#pragma unroll 1
    for (int r0 = j; r0 < 3 * H; r0 += 72) {
        int r1 = r0 + 18, r2 = r0 + 36, r3 = r0 + 54;
        bool b1 = r1 < 3 * H, b2 = r2 < 3 * H, b3 = r3 < 3 * H;
        const float4* W0 = (const float4*)(enc_Wih + (size_t)r0 * H);
        const float4* W1 = (const float4*)(enc_Wih + (size_t)(b1 ? r1 : r0) * H);
        const float4* W2 = (const float4*)(enc_Wih + (size_t)(b2 ? r2 : r0) * H);
        const float4* W3 = (const float4*)(enc_Wih + (size_t)(b3 ? r3 : r0) * H);
        float a0 = 0.f, a1 = 0.f, a2 = 0.f, a3 = 0.f;
#pragma unroll
        for (int i = 0; i < 8; i++) {
            float4 w0 = W0[lane + 32 * i];
            float4 w1 = W1[lane + 32 * i];
            float4 w2 = W2[lane + 32 * i];
            float4 w3 = W3[lane + 32 * i];
            a0 += dot4(w0, ev[i]);
            a1 += dot4(w1, ev[i]);
            a2 += dot4(w2, ev[i]);
            a3 += dot4(w3, ev[i]);
        }
        a0 = wredsum(a0);
        a1 = wredsum(a1);
        a2 = wredsum(a2);
        a3 = wredsum(a3);
        if (lane == 0) {
            gx[r0] = a0;
            if (b1) gx[r1] = a1;
            if (b2) gx[r2] = a2;
            if (b3) gx[r3] = a3;
        }
    }
}

// Encoder GRU step using precomputed gix: Whh@h k-split across warp pairs.
__device__ __forceinline__ void gru_phase_enc(
    const float* __restrict__ Whh,
    const float* __restrict__ bih, const float* __restrict__ bhh,
    const float* __restrict__ h, float* __restrict__ ho, int t, Smem* sm)
{
    int wib = threadIdx.x >> 5;
    int lane = threadIdx.x & 31;
    int wp = wib & 7;
    bool lo = (wib < 7);
    bool hi = (wib >= 8 && wib < 15);
    int row = wp * GRID + (int)blockIdx.x;
    bool act = (lo || hi) && row < H;

    float hr = 0.f, hz = 0.f, hn = 0.f;
    if (act) {
        const float4* h4 = (const float4*)h;
        const float4* W0 = (const float4*)(Whh + (size_t)row * H);
        const float4* W1 = (const float4*)(Whh + (size_t)(row + H) * H);
        const float4* W2 = (const float4*)(Whh + (size_t)(row + 2 * H) * H);
        int k0 = lo ? 0 : 128;
#pragma unroll 4
        for (int k = k0 + lane; k < k0 + 128; k += 32) {
            float4 hv = h4[k];
            hr += dot4(W0[k], hv);
            hz += dot4(W1[k], hv);
            hn += dot4(W2[k], hv);
        }
        hr = wredsum(hr); hz = wredsum(hz); hn = wredsum(hn);
        if (hi && lane == 0) {
            sm->gi[wp][0] = hr; sm->gi[wp][1] = hz; sm->gi[wp][2] = hn;
        }
    }
    __syncthreads();
    if (act && lo && lane == 0) {
        const float* gx = g_gix + (size_t)t * (3 * H);
        float ir  = gx[row]         + bih[row];
        float iz  = gx[row + H]     + bih[row + H];
        float inn = gx[row + 2 * H] + bih[row + 2 * H];
        float HR = hr + sm->gi[wp][0] + bhh[row];
        float HZ = hz + sm->gi[wp][1] + bhh[row + H];
        float HN = hn + sm->gi[wp][2] + bhh[row + 2 * H];
        float r = 1.f / (1.f + expf(-(ir + HR)));
        float z = 1.f / (1.f + expf(-(iz + HZ)));
        float n = tanhf(inn + r * HN);
        float hnew = (1.f - z) * n + z * h[row];
        ho[row] = hnew;
        g_enc_T[(size_t)row * ATTP + t] = hnew;
    }
}

// one-time after encoder: M[i][t] = dot(comb_W[i, H:2H], enc_out[t])
__device__ __forceinline__ void build_M(const float* __restrict__ comb_W)
{
    int wib = threadIdx.x >> 5;
    int lane = threadIdx.x & 31;
    if (wib >= 7) return;
    int row = wib * GRID + (int)blockIdx.x;
    if (row >= H) return;

    const float4* W2 = (const float4*)(comb_W + (size_t)row * 2 * H + H);
    float a0 = 0.f, a1 = 0.f, a2 = 0.f, a3 = 0.f, a4 = 0.f;
#pragma unroll 2
    for (int j4 = 0; j4 < H4; j4++) {
        float4 w = W2[j4];
        const float* E = g_enc_T + (size_t)(j4 * 4) * ATTP + lane;
#pragma unroll
        for (int c = 0; c < 4; c++) {
            float wc = (c == 0) ? w.x : (c == 1) ? w.y : (c == 2) ? w.z : w.w;
            const float* Ec = E + (size_t)c * ATTP;
            a0 += wc * Ec[0];
            a1 += wc * Ec[32];
            a2 += wc * Ec[64];
            a3 += wc * Ec[96];
            a4 += wc * Ec[128];
        }
    }
    float* Mr = g_M + (size_t)row * ATTP;
    Mr[lane]       = a0;
    Mr[lane + 32]  = a1;
    Mr[lane + 64]  = a2;
    Mr[lane + 96]  = a3;
    Mr[lane + 128] = a4;
}

// Whh@h gate sums for row wp (full k), writes sm->gh[wp] (+bhh)
__device__ __forceinline__ void whh_dots(
    const float* __restrict__ Whh, const float* __restrict__ bhh,
    const float* __restrict__ h, int wp, int lane, Smem* sm)
{
    int row = wp * GRID + (int)blockIdx.x;
    if (row >= H) return;
    const float4* h4 = (const float4*)h;
    const float4* W0 = (const float4*)(Whh + (size_t)row * H);
    const float4* W1 = (const float4*)(Whh + (size_t)(row + H) * H);
    const float4* W2 = (const float4*)(Whh + (size_t)(row + 2 * H) * H);
    float hr = 0.f, hz = 0.f, hn = 0.f;
#pragma unroll 4
    for (int k = lane; k < H4; k += 32) {
        float4 hv = h4[k];
        hr += dot4(W0[k], hv);
        hz += dot4(W1[k], hv);
        hn += dot4(W2[k], hv);
    }
    hr = wredsum(hr); hz = wredsum(hz); hn = wredsum(hn);
    if (lane == 0) {
        sm->gh[wp][0] = hr + bhh[row];
        sm->gh[wp][1] = hz + bhh[row + H];
        sm->gh[wp][2] = hn + bhh[row + 2 * H];
    }
}

// Phase A: softmax (w15) + comb rows k-split across warp pairs (w0-6 / w8-14).
__device__ __forceinline__ void comb_phase(
    const float* __restrict__ comb_W, const float* __restrict__ comb_b,
    const float* __restrict__ dec_emb, Smem* sm)
{
    int wib = threadIdx.x >> 5;
    int lane = threadIdx.x & 31;
    int tok = sm->tk;

    if (wib == 15) {
        float v[5];
        float mx = -INFINITY;
#pragma unroll
        for (int k = 0; k < 5; k++) {
            int idx = lane + 32 * k;
            v[k] = (idx < ATT) ? g_attn[idx] : -INFINITY;
            mx = fmaxf(mx, v[k]);
        }
        mx = wredmax(mx);
        float s = 0.f;
#pragma unroll
        for (int k = 0; k < 5; k++) {
            int idx = lane + 32 * k;
            float e = (idx < ATT) ? expf(v[k] - mx) : 0.f;
            sm->e[idx] = e;
            s += e;
        }
        s = wredsum(s);
        if (lane == 0) sm->bf[0] = 1.f / s;
    }

    int wp = wib & 7;
    bool lo = (wib < 7);
    bool hi = (wib >= 8 && wib < 15);
    int row = wp * GRID + (int)blockIdx.x;
    bool act = (lo || hi) && row < H;

    float a = 0.f;
    if (act) {
        const float4* W  = (const float4*)(comb_W + (size_t)row * 2 * H);
        const float4* e4 = (const float4*)(dec_emb + (size_t)tok * H);
        int k0 = lo ? 0 : 128;
#pragma unroll 4
        for (int k = k0 + lane; k < k0 + 128; k += 32) a += dot4(W[k], e4[k]);
        if (hi) {
            a = wredsum(a);
            if (lane == 0) sm->ca[wp] = a;
        }
    }
    __syncthreads();
    if (act && lo) {
        const float* Mr = g_M + (size_t)row * ATTP;
        float b = 0.f;
#pragma unroll
        for (int k = 0; k < 5; k++) {
            int t = lane + 32 * k;
            b += sm->e[t] * Mr[t];
        }
        float tot = a + b * sm->bf[0];
        tot = wredsum(tot);
        if (lane == 0)
            g_comb[row] = fmaxf(tot + sm->ca[wp] + comb_b[row], 0.f);
    }
}

// Phase B: gru finish — Wih@comb k-split + gates; warps 7,15 write prev output;
// epilogue reduces this CTA's |hnew| values into g_hmax[cta].
__device__ __forceinline__ void gru_fin_phase(
    const float* __restrict__ dec_Wih, const float* __restrict__ dec_bih,
    const float* __restrict__ hc, float* __restrict__ hn_out,
    float* __restrict__ out, int step, Smem* sm)
{
    int wib = threadIdx.x >> 5;
    int lane = threadIdx.x & 31;
    int wp = wib & 7;
    bool lo = (wib < 7);
    bool hi = (wib >= 8 && wib < 15);
    int row = wp * GRID + (int)blockIdx.x;
    bool act = (lo || hi) && row < H;

    if (threadIdx.x < 8) sm->ca[threadIdx.x] = 0.f;   // |hnew| slots

    float ir = 0.f, iz = 0.f, inn = 0.f;
    if (act) {
        const float4* x4 = (const float4*)g_comb;
        const float4* W0 = (const float4*)(dec_Wih + (size_t)row * H);
        const float4* W1 = (const float4*)(dec_Wih + (size_t)(row + H) * H);
        const float4* W2 = (const float4*)(dec_Wih + (size_t)(row + 2 * H) * H);
        int k0 = lo ? 0 : 128;
#pragma unroll 4
        for (int k = k0 + lane; k < k0 + 128; k += 32) {
            float4 xv = x4[k];
            ir  += dot4(W0[k], xv);
            iz  += dot4(W1[k], xv);
            inn += dot4(W2[k], xv);
        }
        ir = wredsum(ir); iz = wredsum(iz); inn = wredsum(inn);
        if (hi && lane == 0) {
            sm->gi[wp][0] = ir; sm->gi[wp][1] = iz; sm->gi[wp][2] = inn;
        }
    } else if ((wib == 7 || wib == 15) && step > 0) {
        float lse = sm->bf[3];
        int wt = (wib == 7 ? lane : 32 + lane);
        for (int g = (int)blockIdx.x * 64 + wt; g < VOUT; g += GRID * 64)
            out[(size_t)(step - 1) * VOUT + g] = g_logits[g] - lse;
    }
    __syncthreads();
    if (act && lo && lane == 0) {
        float IR = ir + sm->gi[wp][0] + dec_bih[row];
        float IZ = iz + sm->gi[wp][1] + dec_bih[row + H];
        float IN = inn + sm->gi[wp][2] + dec_bih[row + 2 * H];
        float hr = sm->gh[wp][0];
        float hz = sm->gh[wp][1];
        float hn = sm->gh[wp][2];
        float r = 1.f / (1.f + expf(-(IR + hr)));
        float z = 1.f / (1.f + expf(-(IZ + hz)));
        float n = tanhf(IN + r * hn);
        float hnew = (1.f - z) * n + z * hc[row];
        hn_out[row] = hnew;
        sm->ca[wp] = fabsf(hnew);
    }
    __syncthreads();
    if (wib == 0) {
        float m = (lane < 8) ? sm->ca[lane] : 0.f;
        m = wredmax(m);
        if (lane == 0) g_hmax[blockIdx.x] = m;
    }
}

// Phase C: logits GEMV on int8 weights; h scale from g_hmax.
// Epilogue: warps 0-6 sumexp; warps 8,9 fp32-recheck CTA top-2 -> g_pfix.
__device__ __forceinline__ void logits_phase(
    const float* __restrict__ out_b, const float* __restrict__ out_W,
    const float* __restrict__ h, Smem* sm)
{
    int tid = threadIdx.x, lane = tid & 31, wib = tid >> 5;
    int gw = (int)blockIdx.x * WPB + wib;

    // only slot 13 can correspond to an OOB row; init just those
    if (tid < WPB) sm->slot[tid * MAXSLOT + 13] = -INFINITY;

    if (wib == 0) {               // global maxabs from per-CTA partials
        float m = 0.f;
#pragma unroll
        for (int k = 0; k < 5; k++) {
            int idx = lane + 32 * k;
            if (idx < GRID) m = fmaxf(m, g_hmax[idx]);
        }
        m = wredmax(m);
        if (lane == 0) {
            sm->bf[1] = m * (1.f / 127.f);
            sm->bf[2] = (m > 0.f) ? (127.f / m) : 0.f;
        }
    }
    __syncthreads();
    float hs   = sm->bf[1];
    float hinv = sm->bf[2];

    if (tid < 256) sm->hq[tid] = q4(((const float4*)h)[tid], hinv);
    __syncthreads();

    const uint4* hq4 = (const uint4*)sm->hq;
    uint4 hA = hq4[lane];
    uint4 hB = hq4[lane + 32];

    float* slotp = sm->slot + wib * MAXSLOT;

#pragma unroll
    for (int b = 0; b < 2; b++) {
        int base = b * 7;
        uint4 wA[7], wB[7];
        int rr[7];
        bool okk[7];
#pragma unroll
        for (int j = 0; j < 7; j++) {
            int r = gw + (base + j) * NWARPS;
            okk[j] = (r < VOUT);
            if (!okk[j]) r = gw;
            rr[j] = r;
            const uint4* Wq = (const uint4*)(g_wq + (size_t)r * 256);
            wA[j] = __ldg(&Wq[lane]);
            wB[j] = __ldg(&Wq[lane + 32]);
        }
#pragma unroll
        for (int j = 0; j < 7; j++) {
            int acc = 0;
            acc = __dp4a((int)wA[j].x, (int)hA.x, acc);
            acc = __dp4a((int)wA[j].y, (int)hA.y, acc);
            acc = __dp4a((int)wA[j].z, (int)hA.z, acc);
            acc = __dp4a((int)wA[j].w, (int)hA.w, acc);
            acc = __dp4a((int)wB[j].x, (int)hB.x, acc);
            acc = __dp4a((int)wB[j].y, (int)hB.y, acc);
            acc = __dp4a((int)wB[j].z, (int)hB.z, acc);
            acc = __dp4a((int)wB[j].w, (int)hB.w, acc);
            acc = wredsumi(acc);
            if (lane == 0 && okk[j]) {
                int r = rr[j];
                float lg = (float)acc * (g_wscale[r] * hs) + out_b[r];
                g_logits[r] = lg;
                slotp[base + j] = lg;
            }
        }
    }

    if (lane == 0) {
        unsigned long long c0 = 0, c1 = 0, c2 = 0, c3 = 0;
#pragma unroll
        for (int n = 0; n < MAXSLOT; n++) {
            int row = gw + n * NWARPS;
            if (row < VOUT) {
                unsigned long long p = packf(slotp[n], row);
                top4_ins(c0, c1, c2, c3, p);
            }
        }
        sm->wtop[wib][0] = c0; sm->wtop[wib][1] = c1;
        sm->wtop[wib][2] = c2; sm->wtop[wib][3] = c3;
    }
    __syncthreads();

    if (wib == 0) {
        unsigned long long a0 = 0, a1 = 0, a2 = 0, a3 = 0;
        if (lane < WPB) {
            a0 = sm->wtop[lane][0]; a1 = sm->wtop[lane][1];
            a2 = sm->wtop[lane][2]; a3 = sm->wtop[lane][3];
        }
        int pos = 0;
        unsigned long long t[4];
#pragma unroll
        for (int k = 0; k < 4; k++) {
            unsigned long long head = (pos == 0) ? a0 : (pos == 1) ? a1 :
                                      (pos == 2) ? a2 : (pos == 3) ? a3 : 0ull;
            unsigned long long m = wredmaxu64(head);
            t[k] = m;
            if (head == m && pos < 4) pos++;
        }
        if (lane == 0) {
            g_ptop1[blockIdx.x] = t[0];
            sm->bu = t[0];
            sm->top4[0] = t[0];
            sm->top4[1] = t[1];
        }
    }
    __syncthreads();

    // warps 0-6: CTA sumexp wrt CTA int8 max; warps 8,9: fp32 recheck top-2
    if (wib < 7) {
        float m = unpack_max(sm->bu);
        float e = expf(sm->slot[tid] - m);     // OOB slots are -inf -> 0
        e = wredsum(e);
        if (lane == 0) sm->red[wib] = e;
    } else if (wib == 8 || wib == 9) {
        int k = wib - 8;
        int rk = unpack_idx(sm->top4[k]);
        const float4* W = (const float4*)(out_W + (size_t)rk * H);
        const float4* h4 = (const float4*)h;
        float a = 0.f;
#pragma unroll 4
        for (int kk = lane; kk < H4; kk += 32) a += dot4(W[kk], h4[kk]);
        a = wredsum(a);
        if (lane == 0) g_pfix[blockIdx.x][k] = packf(a + out_b[rk], rk);
    }
    __syncthreads();
    if (tid == 0) {
        float S = 0.f;
#pragma unroll
        for (int i = 0; i < 7; i++) S += sm->red[i];
        g_psum[blockIdx.x] = S;
    }
}

// Phase D: warps 0-5 (named barrier): lse + fp32 tok merge + attn prep;
// warps 6-12: Whh@hn for NEXT step.
__device__ __forceinline__ void out_phase(
    const float* __restrict__ attn_W, const float* __restrict__ attn_b,
    const float* __restrict__ dec_emb, const float* __restrict__ h,
    const float* __restrict__ dec_Whh, const float* __restrict__ dec_bhh,
    Smem* sm)
{
    int tid = threadIdx.x, lane = tid & 31, wib = tid >> 5;

    if (wib >= 6 && wib < 13) {
        whh_dots(dec_Whh, dec_bhh, h, wib - 6, lane, sm);
        return;
    }
    if (wib >= 13) return;

    if (wib == 0) {
        // lse: M from int8 per-CTA tops; S from psum rebased to M
        unsigned long long pm[5];
        float ps[5];
        unsigned long long best = 0ull;
        unsigned long long fx0 = 0ull, fx1 = 0ull, fx2 = 0ull, fx3 = 0ull;
#pragma unroll
        for (int k = 0; k < 5; k++) {
            int cc = lane + 32 * k;
            if (cc < GRID) {
                pm[k] = g_ptop1[cc];
                ps[k] = g_psum[cc];
                if (pm[k] > best) best = pm[k];
                top4_ins(fx0, fx1, fx2, fx3, g_pfix[cc][0]);
                top4_ins(fx0, fx1, fx2, fx3, g_pfix[cc][1]);
            } else { pm[k] = 0ull; ps[k] = 0.f; }
        }
        best = wredmaxu64(best);
        float M = unpack_max(best);
        float S = 0.f;
#pragma unroll
        for (int k = 0; k < 5; k++) {
            int cc = lane + 32 * k;
            if (cc < GRID) S += ps[k] * expf(unpack_max(pm[k]) - M);
        }
        S = wredsum(S);
        unsigned long long w = wredmaxu64(fx0);   // global fp32-exact argmax
        if (lane == 0) {
            sm->bf[3] = M + logf(S);
            sm->tk = unpack_idx(w);
        }
    }
    BAR6();
    int tok = sm->tk;

    if ((int)blockIdx.x < ATT) {
        int r = (int)blockIdx.x;
        if (wib == 4) {
            const float4* W  = (const float4*)(attn_W + (size_t)r * 2 * H);
            const float4* e4 = (const float4*)(dec_emb + (size_t)tok * H);
            float a = 0.f;
#pragma unroll 4
            for (int k = lane; k < H4; k += 32) a += dot4(W[k], e4[k]);
            a = wredsum(a);
            if (lane == 0) sm->bf[1] = a;
        } else if (wib == 5) {
            const float4* W  = (const float4*)(attn_W + (size_t)r * 2 * H + H);
            const float4* h4 = (const float4*)h;
            float a = 0.f;
#pragma unroll 4
            for (int k = lane; k < H4; k += 32) a += dot4(W[k], h4[k]);
            a = wredsum(a);
            if (lane == 0) sm->bf[2] = a;
        }
    }
    BAR6();
    if (wib == 4 && lane == 0 && (int)blockIdx.x < ATT)
        g_attn[blockIdx.x] = sm->bf[1] + sm->bf[2] + attn_b[blockIdx.x];
}

// ---------------- the single persistent kernel ----------------
__global__ void __launch_bounds__(BLOCK, 1) k_all(
    const int* __restrict__ tokens,
    const float* __restrict__ enc_emb,
    const float* __restrict__ enc_Wih, const float* __restrict__ enc_Whh,
    const float* __restrict__ enc_bih, const float* __restrict__ enc_bhh,
    const float* __restrict__ dec_emb,
    const float* __restrict__ attn_W, const float* __restrict__ attn_b,
    const float* __restrict__ comb_W, const float* __restrict__ comb_b,
    const float* __restrict__ dec_Wih, const float* __restrict__ dec_Whh,
    const float* __restrict__ dec_bih, const float* __restrict__ dec_bhh,
    const float* __restrict__ out_W, const float* __restrict__ out_b,
    float* __restrict__ out)
{
    __shared__ Smem sm;
    int tid = threadIdx.x;
    int wib = tid >> 5, lane = tid & 31;
    unsigned bgen = 0;

    // one-time: quantize out_W to int8 with per-row scale (warp per row)
    {
        int gw = (int)blockIdx.x * WPB + wib;
#pragma unroll 1
        for (int n = 0; n < MAXSLOT; n++) {
            int r = gw + n * NWARPS;
            if (r >= VOUT) break;
            const float4* wr = (const float4*)(out_W + (size_t)r * H);
            float4 v[8];
            float mx = 0.f;
#pragma unroll
            for (int i = 0; i < 8; i++) {
                v[i] = __ldcs(&wr[lane + 32 * i]);
                mx = fmaxf(mx, fmaxf(fmaxf(fabsf(v[i].x), fabsf(v[i].y)),
                                     fmaxf(fabsf(v[i].z), fabsf(v[i].w))));
            }
            mx = wredmax(mx);
            float inv = (mx > 0.f) ? (127.f / mx) : 0.f;
            unsigned* dst = g_wq + (size_t)r * 256;
#pragma unroll
            for (int i = 0; i < 8; i++)
                dst[lane + 32 * i] = q4(v[i], inv);
            if (lane == 0) g_wscale[r] = mx * (1.f / 127.f);
        }
    }

    // one-time: precompute gix = enc_Wih @ emb[tokens] for all timesteps
    build_gix(enc_Wih, enc_emb, tokens);

    // init: h0 = 0, zero enc_T (padding columns must be 0)
    {
        int gt = (int)blockIdx.x * BLOCK + tid;
        if (gt < H) g_h[0][gt] = 0.f;
        for (int i = gt; i < H * ATTP; i += GRID * BLOCK) g_enc_T[i] = 0.f;
    }
    gsync(bgen);

    // ---- encoder: Whh-only steps using precomputed gix ----
    for (int t = 0; t < ML; t++) {
        gru_phase_enc(enc_Whh, enc_bih, enc_bhh,
                      g_h[t & 1], g_h[(t & 1) ^ 1], t, &sm);
        gsync(bgen);
    }
    // final encoder hidden in g_h[0]

    // ---- prep phase: build M (w0-6) + attn logits (w8,9) + Whh@h0 (w7,10-15) ----
    build_M(comb_W);
    if (wib == 7) whh_dots(dec_Whh, dec_bhh, g_h[0], 6, lane, &sm);
    else if (wib >= 10) whh_dots(dec_Whh, dec_bhh, g_h[0], wib - 10, lane, &sm);
    if ((int)blockIdx.x < ATT) {
        int r = (int)blockIdx.x;
        if (wib == 8) {
            const float4* W  = (const float4*)(attn_W + (size_t)r * 2 * H);
            const float4* e4 = (const float4*)dec_emb;
            float a = 0.f;
#pragma unroll 4
            for (int k = lane; k < H4; k += 32) a += dot4(W[k], e4[k]);
            a = wredsum(a);
            if (lane == 0) sm.bf[1] = a;
        } else if (wib == 9) {
            const float4* W  = (const float4*)(attn_W + (size_t)r * 2 * H + H);
            const float4* h4 = (const float4*)g_h[0];
            float a = 0.f;
#pragma unroll 4
            for (int k = lane; k < H4; k += 32) a += dot4(W[k], h4[k]);
            a = wredsum(a);
            if (lane == 0) sm.bf[2] = a;
        }
    }
    __syncthreads();
    if ((int)blockIdx.x < ATT && tid == 0)
        g_attn[blockIdx.x] = sm.bf[1] + sm.bf[2] + attn_b[blockIdx.x];
    if (tid == 0) sm.tk = 0;
    gsync(bgen);

    // ---- decoder: 4 barriers per step ----
    for (int s = 0; s < ML; s++) {
        const float* hc = g_h[s & 1];
        float* hn = g_h[(s & 1) ^ 1];

        comb_phase(comb_W, comb_b, dec_emb, &sm);              gsync(bgen);
        gru_fin_phase(dec_Wih, dec_bih, hc, hn, out, s, &sm);  gsync(bgen);
        logits_phase(out_b, out_W, hn, &sm);                   gsync(bgen);
        out_phase(attn_W, attn_b, dec_emb, hn,
                  dec_Whh, dec_bhh, &sm);                      gsync(bgen);
    }

    // final step's output (lse from last D, g_logits stable)
    {
        float lse = sm.bf[3];
        int g = (int)blockIdx.x * BLOCK + tid;
        if (g < VOUT) out[(size_t)(ML - 1) * VOUT + g] = g_logits[g] - lse;
    }
}

// ---------------- host launcher ----------------
extern "C" void kernel_launch(void* const* d_in, const int* in_sizes, int n_in,
                              void* d_out, int out_size)
{
    const int*   tokens  = (const int*)  d_in[0];
    // d_in[1] = max_length (compile-time ML=128)
    const float* enc_emb = (const float*)d_in[2];
    const float* enc_Wih = (const float*)d_in[3];
    const float* enc_Whh = (const float*)d_in[4];
    const float* enc_bih = (const float*)d_in[5];
    const float* enc_bhh = (const float*)d_in[6];
    const float* dec_emb = (const float*)d_in[7];
    const float* attn_W  = (const float*)d_in[8];
    const float* attn_b  = (const float*)d_in[9];
    const float* comb_W  = (const float*)d_in[10];
    const float* comb_b  = (const float*)d_in[11];
    const float* dec_Wih = (const float*)d_in[12];
    const float* dec_Whh = (const float*)d_in[13];
    const float* dec_bih = (const float*)d_in[14];
    const float* dec_bhh = (const float*)d_in[15];
    const float* out_W   = (const float*)d_in[16];
    const float* out_b   = (const float*)d_in[17];
    float* out = (float*)d_out;

    k_all<<<GRID, BLOCK>>>(tokens, enc_emb, enc_Wih, enc_Whh, enc_bih, enc_bhh,
                           dec_emb, attn_W, attn_b, comb_W, comb_b,
                           dec_Wih, dec_Whh, dec_bih, dec_bhh,
                           out_W, out_b, out);
}